// round 4
// baseline (speedup 1.0000x reference)
#include <cuda_runtime.h>
#include <math.h>
#include <mma.h>

using namespace nvcuda;

#define HW     128
#define BATCH  2
#define CH     128
#define NPIX   (HW*HW)            // 16384
#define ITERS  10
#define CSH    272                // padded channel stride for hcat (multiple of 8, 16B-aligned stride)

// ---------------- scratch (static device allocations; no cudaMalloc) ----------------
__device__ float g_lf0 [BATCH*CH*NPIX];
__device__ float g_lf1 [BATCH*CH*NPIX];
__device__ float g_nA  [BATCH*NPIX*CH];      // NHWC buffer A
__device__ float g_nB  [BATCH*NPIX*CH];      // NHWC buffer B
__device__ float g_x   [BATCH*NPIX*CH];      // channel-last attention input
__device__ float g_q   [BATCH*NPIX*CH];
__device__ float g_k   [BATCH*NPIX*CH];
__device__ float g_flow[BATCH*2*NPIX];
__device__ float g_fi  [BATCH*2*NPIX];
__device__ float g_hcat[BATCH*CSH*NPIX];     // NHWC padded
__device__ float g_h2  [BATCH*64*NPIX];      // NCHW
__device__ float g_wt1 [9*CH*CH];            // [tap][cin][cout]
__device__ float g_wt2 [9*CH*CH];
__device__ float g_wtc1[9*CSH*CH];
__device__ float g_wtc2[9*CH*64];

// ---------------- helpers ----------------
__device__ __forceinline__ float gelu_f(float v) {
    return 0.5f * v * (1.0f + erff(v * 0.70710678118654752f));
}
__device__ __forceinline__ float sigmoid_f(float v) {
    return 1.0f / (1.0f + expf(-v));
}

#define ACT_NONE 0
#define ACT_GELU 1
#define ACT_SIGM 2

#define LAYOUT_NHWC 0
#define LAYOUT_NCHW 1

// ---------------- weight transpose: w[cout][cin][3][3] -> wt[tap][cinPad][cout] ----------------
__global__ void wtrans_kernel(const float* __restrict__ w, float* __restrict__ wt,
                              int Cin, int CinPad, int Cout)
{
    int i = blockIdx.x * 256 + threadIdx.x;
    int total = 9 * CinPad * Cout;
    if (i >= total) return;
    int tap = i / (CinPad * Cout);
    int rem = i % (CinPad * Cout);
    int ci  = rem / Cout;
    int co  = rem % Cout;
    wt[i] = (ci < Cin) ? w[((size_t)co * Cin + ci) * 9 + tap] : 0.f;
}

// ---------------- NCHW -> NHWC transpose (C = 128) ----------------
__global__ __launch_bounds__(256) void nchw2nhwc_kernel(
    const float* __restrict__ in, float* __restrict__ out)
{
    __shared__ float t[32][33];
    const int p0 = blockIdx.x * 32;
    const int c0 = blockIdx.y * 32;
    const int b  = blockIdx.z;
    const int tx = threadIdx.x & 31, ty = threadIdx.x >> 5;   // 32 x 8
    #pragma unroll
    for (int i = 0; i < 4; i++)
        t[ty + i * 8][tx] = in[((size_t)b * CH + c0 + ty + i * 8) * NPIX + p0 + tx];
    __syncthreads();
    #pragma unroll
    for (int i = 0; i < 4; i++)
        out[((size_t)b * NPIX + p0 + ty + i * 8) * CH + c0 + tx] = t[tx][ty + i * 8];
}

// ---------------- tf32x3 implicit-GEMM 3x3 conv ----------------
// Input NHWC (stride CS_in), weights wt[tap][CinPad][Cout], output NHWC or NCHW.
// Block: 256 thr, tile = 1 image row (128 px) x 64 couts. grid (Cout/64, HW, B).
#define CONV_A_HI 0
#define CONV_A_LO 3120            // 3*130*8
#define CONV_B_HI 6240
#define CONV_B_LO 10848           // + 9*8*64
#define CONV_SMEM_FLOATS 15456
#define CONV_SMEM_BYTES (CONV_SMEM_FLOATS*4)

__global__ __launch_bounds__(256) void conv3x3_tc_kernel(
    const float* __restrict__ X, const float* __restrict__ Wt,
    const float* __restrict__ bias, float* __restrict__ out,
    int CinPad, int CS_in, int Cout, int CS_out, int act, int layout)
{
    extern __shared__ float sm[];
    float* As_hi = sm + CONV_A_HI;
    float* As_lo = sm + CONV_A_LO;
    float* Bs_hi = sm + CONV_B_HI;
    float* Bs_lo = sm + CONV_B_LO;

    const int tid = threadIdx.x;
    const int wid = tid >> 5;
    const int wm = wid & 3;          // m offset 32*wm
    const int wn = wid >> 2;         // n offset 32*wn
    const int n0 = blockIdx.x * 64;
    const int y  = blockIdx.y;
    const int b  = blockIdx.z;

    wmma::fragment<wmma::accumulator, 16, 16, 8, float> acc[2][2];
    #pragma unroll
    for (int mi = 0; mi < 2; mi++)
        #pragma unroll
        for (int ni = 0; ni < 2; ni++)
            wmma::fill_fragment(acc[mi][ni], 0.f);

    const int nslices = CinPad >> 3;
    for (int cs = 0; cs < nslices; cs++) {
        const int c0 = cs * 8;
        // stage A: rows y-1..y+1, cols -1..128 (130), 8 cin, hi/lo
        for (int i = tid; i < 780; i += 256) {
            int pos = i >> 1, half = i & 1;
            int r = pos / 130, c = pos % 130;
            int gy = y - 1 + r, gx = c - 1;
            float4 v = make_float4(0.f, 0.f, 0.f, 0.f);
            if ((unsigned)gy < (unsigned)HW && (unsigned)gx < (unsigned)HW)
                v = *(const float4*)&X[((size_t)b * NPIX + gy * HW + gx) * CS_in + c0 + half * 4];
            int o = pos * 8 + half * 4;
            float h0 = wmma::__float_to_tf32(v.x);
            float h1 = wmma::__float_to_tf32(v.y);
            float h2 = wmma::__float_to_tf32(v.z);
            float h3 = wmma::__float_to_tf32(v.w);
            As_hi[o+0] = h0; As_hi[o+1] = h1; As_hi[o+2] = h2; As_hi[o+3] = h3;
            As_lo[o+0] = wmma::__float_to_tf32(v.x - h0);
            As_lo[o+1] = wmma::__float_to_tf32(v.y - h1);
            As_lo[o+2] = wmma::__float_to_tf32(v.z - h2);
            As_lo[o+3] = wmma::__float_to_tf32(v.w - h3);
        }
        // stage B: 9 taps x 8 cin x 64 cout, hi/lo
        for (int i = tid; i < 1152; i += 256) {
            int tap = i >> 7;              // /128
            int rem = i & 127;
            int ci = rem >> 4, n4 = rem & 15;
            float4 v = *(const float4*)&Wt[((size_t)(tap * CinPad) + c0 + ci) * Cout + n0 + n4 * 4];
            int o = (tap * 8 + ci) * 64 + n4 * 4;
            float h0 = wmma::__float_to_tf32(v.x);
            float h1 = wmma::__float_to_tf32(v.y);
            float h2 = wmma::__float_to_tf32(v.z);
            float h3 = wmma::__float_to_tf32(v.w);
            Bs_hi[o+0] = h0; Bs_hi[o+1] = h1; Bs_hi[o+2] = h2; Bs_hi[o+3] = h3;
            Bs_lo[o+0] = wmma::__float_to_tf32(v.x - h0);
            Bs_lo[o+1] = wmma::__float_to_tf32(v.y - h1);
            Bs_lo[o+2] = wmma::__float_to_tf32(v.z - h2);
            Bs_lo[o+3] = wmma::__float_to_tf32(v.w - h3);
        }
        __syncthreads();

        #pragma unroll
        for (int tap = 0; tap < 9; tap++) {
            const int dy = tap / 3, dxi = tap % 3;
            wmma::fragment<wmma::matrix_b, 16, 16, 8, wmma::precision::tf32, wmma::row_major> bh[2], bl[2];
            #pragma unroll
            for (int ni = 0; ni < 2; ni++) {
                int boff = tap * 512 + 32 * wn + ni * 16;
                wmma::load_matrix_sync(bh[ni], Bs_hi + boff, 64);
                wmma::load_matrix_sync(bl[ni], Bs_lo + boff, 64);
            }
            #pragma unroll
            for (int mi = 0; mi < 2; mi++) {
                int m = 32 * wm + mi * 16;
                int aoff = (dy * 130 + m + dxi) * 8;
                wmma::fragment<wmma::matrix_a, 16, 16, 8, wmma::precision::tf32, wmma::row_major> ah, al;
                wmma::load_matrix_sync(ah, As_hi + aoff, 8);
                wmma::load_matrix_sync(al, As_lo + aoff, 8);
                #pragma unroll
                for (int ni = 0; ni < 2; ni++) {
                    wmma::mma_sync(acc[mi][ni], ah, bl[ni], acc[mi][ni]);
                    wmma::mma_sync(acc[mi][ni], al, bh[ni], acc[mi][ni]);
                    wmma::mma_sync(acc[mi][ni], ah, bh[ni], acc[mi][ni]);
                }
            }
        }
        __syncthreads();
    }

    // epilogue: store fragments to smem [128][64], then bias+act+write
    float* Cs = sm;
    #pragma unroll
    for (int mi = 0; mi < 2; mi++)
        #pragma unroll
        for (int ni = 0; ni < 2; ni++)
            wmma::store_matrix_sync(&Cs[(32 * wm + mi * 16) * 64 + 32 * wn + ni * 16],
                                    acc[mi][ni], 64, wmma::mem_row_major);
    __syncthreads();

    if (layout == LAYOUT_NHWC) {
        for (int i = tid; i < 128 * 16; i += 256) {
            int x = i >> 4, j = i & 15;
            float4 v = *(float4*)&Cs[x * 64 + j * 4];
            int cg = n0 + j * 4;
            v.x += bias[cg+0]; v.y += bias[cg+1]; v.z += bias[cg+2]; v.w += bias[cg+3];
            if (act == ACT_GELU) { v.x = gelu_f(v.x); v.y = gelu_f(v.y); v.z = gelu_f(v.z); v.w = gelu_f(v.w); }
            *(float4*)&out[((size_t)b * NPIX + y * HW + x) * CS_out + cg] = v;
        }
    } else {
        for (int i = tid; i < 64 * 32; i += 256) {
            int co = i >> 5, xf4 = i & 31;
            float bv = bias[n0 + co];
            float4 v;
            v.x = Cs[(xf4 * 4 + 0) * 64 + co] + bv;
            v.y = Cs[(xf4 * 4 + 1) * 64 + co] + bv;
            v.z = Cs[(xf4 * 4 + 2) * 64 + co] + bv;
            v.w = Cs[(xf4 * 4 + 3) * 64 + co] + bv;
            if (act == ACT_GELU) { v.x = gelu_f(v.x); v.y = gelu_f(v.y); v.z = gelu_f(v.z); v.w = gelu_f(v.w); }
            *(float4*)&out[((size_t)(b * CS_out + n0 + co) * HW + y) * HW + xf4 * 4] = v;
        }
    }
}

// ---------------- tf32x3 GEMM for q/k: [32768,128] x W^T[128,128] + bias ----------------
// grid (256, 2): y=0 -> q, y=1 -> k. block 256 thr, tile 128x128.
#define QK_A_HI 0
#define QK_A_LO 1024
#define QK_B_HI 2048
#define QK_B_LO 3072
#define QK_SMEM_FLOATS 16384      // epilogue Cs[128][128] overlay
#define QK_SMEM_BYTES (QK_SMEM_FLOATS*4)

__global__ __launch_bounds__(256) void gemm_qk_tc_kernel(
    const float* __restrict__ X,
    const float* __restrict__ qw, const float* __restrict__ qb,
    const float* __restrict__ kw, const float* __restrict__ kb,
    float* __restrict__ Q, float* __restrict__ Kout)
{
    extern __shared__ float sm[];
    float* As_hi = sm + QK_A_HI;
    float* As_lo = sm + QK_A_LO;
    float* Bs_hi = sm + QK_B_HI;
    float* Bs_lo = sm + QK_B_LO;

    const int tid = threadIdx.x;
    const int wid = tid >> 5;
    const int wm = wid & 3;        // m offset 32*wm
    const int wn = wid >> 2;       // n offset 64*wn
    const int m0 = blockIdx.x * 128;
    const bool isK = (blockIdx.y != 0);
    const float* W    = isK ? kw : qw;
    const float* bias = isK ? kb : qb;
    float* out        = isK ? Kout : Q;

    wmma::fragment<wmma::accumulator, 16, 16, 8, float> acc[2][4];
    #pragma unroll
    for (int mi = 0; mi < 2; mi++)
        #pragma unroll
        for (int ni = 0; ni < 4; ni++)
            wmma::fill_fragment(acc[mi][ni], 0.f);

    for (int cs = 0; cs < 16; cs++) {
        const int c0 = cs * 8;
        // stage A [128][8]
        {
            int row = tid >> 1, half = tid & 1;
            float4 v = *(const float4*)&X[(size_t)(m0 + row) * 128 + c0 + half * 4];
            int o = row * 8 + half * 4;
            float h0 = wmma::__float_to_tf32(v.x);
            float h1 = wmma::__float_to_tf32(v.y);
            float h2 = wmma::__float_to_tf32(v.z);
            float h3 = wmma::__float_to_tf32(v.w);
            As_hi[o+0] = h0; As_hi[o+1] = h1; As_hi[o+2] = h2; As_hi[o+3] = h3;
            As_lo[o+0] = wmma::__float_to_tf32(v.x - h0);
            As_lo[o+1] = wmma::__float_to_tf32(v.y - h1);
            As_lo[o+2] = wmma::__float_to_tf32(v.z - h2);
            As_lo[o+3] = wmma::__float_to_tf32(v.w - h3);
        }
        // stage B [8][128] = W^T slice (W is [cout][cin])
        #pragma unroll
        for (int i = tid; i < 1024; i += 256) {
            int n = i & 127, k = i >> 7;
            float v = W[(size_t)n * 128 + c0 + k];
            float h = wmma::__float_to_tf32(v);
            Bs_hi[k * 128 + n] = h;
            Bs_lo[k * 128 + n] = wmma::__float_to_tf32(v - h);
        }
        __syncthreads();

        wmma::fragment<wmma::matrix_b, 16, 16, 8, wmma::precision::tf32, wmma::row_major> bh[4], bl[4];
        #pragma unroll
        for (int ni = 0; ni < 4; ni++) {
            int boff = 64 * wn + ni * 16;
            wmma::load_matrix_sync(bh[ni], Bs_hi + boff, 128);
            wmma::load_matrix_sync(bl[ni], Bs_lo + boff, 128);
        }
        #pragma unroll
        for (int mi = 0; mi < 2; mi++) {
            int aoff = (32 * wm + mi * 16) * 8;
            wmma::fragment<wmma::matrix_a, 16, 16, 8, wmma::precision::tf32, wmma::row_major> ah, al;
            wmma::load_matrix_sync(ah, As_hi + aoff, 8);
            wmma::load_matrix_sync(al, As_lo + aoff, 8);
            #pragma unroll
            for (int ni = 0; ni < 4; ni++) {
                wmma::mma_sync(acc[mi][ni], ah, bl[ni], acc[mi][ni]);
                wmma::mma_sync(acc[mi][ni], al, bh[ni], acc[mi][ni]);
                wmma::mma_sync(acc[mi][ni], ah, bh[ni], acc[mi][ni]);
            }
        }
        __syncthreads();
    }

    float* Cs = sm;   // [128][128]
    #pragma unroll
    for (int mi = 0; mi < 2; mi++)
        #pragma unroll
        for (int ni = 0; ni < 4; ni++)
            wmma::store_matrix_sync(&Cs[(32 * wm + mi * 16) * 128 + 64 * wn + ni * 16],
                                    acc[mi][ni], 128, wmma::mem_row_major);
    __syncthreads();

    for (int i = tid; i < 128 * 32; i += 256) {
        int px = i >> 5, j = i & 31;
        float4 v = *(float4*)&Cs[px * 128 + j * 4];
        v.x += bias[j*4+0]; v.y += bias[j*4+1]; v.z += bias[j*4+2]; v.w += bias[j*4+3];
        *(float4*)&out[(size_t)(m0 + px) * 128 + j * 4] = v;
    }
}

// ---------------- generic NCHW 3x3 conv (kept for tiny cf3) ----------------
template<int COT>
__global__ __launch_bounds__(256, 2) void conv3x3_kernel(
    const float* __restrict__ in, const float* __restrict__ wgt,
    const float* __restrict__ bias, float* __restrict__ out,
    int Cin, int Cout, int act)
{
    __shared__ float s_in[8][34][34];
    __shared__ float s_w[8][COT][9];

    const int tid = threadIdx.x;
    const int tx = tid & 15, ty = tid >> 4;
    const int x0 = blockIdx.x * 32, y0 = blockIdx.y * 32;
    const int nco = (Cout + COT - 1) / COT;
    const int bb  = blockIdx.z / nco;
    const int co0 = (blockIdx.z % nco) * COT;

    float acc[COT][2][2];
    #pragma unroll
    for (int c = 0; c < COT; c++)
        #pragma unroll
        for (int i = 0; i < 2; i++)
            #pragma unroll
            for (int j = 0; j < 2; j++) acc[c][i][j] = 0.f;

    for (int c0 = 0; c0 < Cin; c0 += 8) {
        for (int idx = tid; idx < 8 * 1156; idx += 256) {
            int ci = idx / 1156;
            int r  = (idx % 1156) / 34;
            int cc = idx % 34;
            int gy = y0 - 1 + r, gx = x0 - 1 + cc;
            int cin = c0 + ci;
            float v = 0.f;
            if (cin < Cin && (unsigned)gy < (unsigned)HW && (unsigned)gx < (unsigned)HW)
                v = in[((size_t)(bb * Cin + cin) * HW + gy) * HW + gx];
            s_in[ci][r][cc] = v;
        }
        for (int idx = tid; idx < 8 * COT * 9; idx += 256) {
            int ci = idx / (COT * 9);
            int co = (idx % (COT * 9)) / 9;
            int k  = idx % 9;
            int cin = c0 + ci, cog = co0 + co;
            float v = 0.f;
            if (cin < Cin && cog < Cout)
                v = wgt[((size_t)cog * Cin + cin) * 9 + k];
            s_w[ci][co][k] = v;
        }
        __syncthreads();

        #pragma unroll
        for (int ci = 0; ci < 8; ci++) {
            float v[4][4];
            #pragma unroll
            for (int i = 0; i < 4; i++)
                #pragma unroll
                for (int j = 0; j < 4; j++)
                    v[i][j] = s_in[ci][ty * 2 + i][tx * 2 + j];
            #pragma unroll
            for (int co = 0; co < COT; co++) {
                float w0 = s_w[ci][co][0], w1 = s_w[ci][co][1], w2 = s_w[ci][co][2];
                float w3 = s_w[ci][co][3], w4 = s_w[ci][co][4], w5 = s_w[ci][co][5];
                float w6 = s_w[ci][co][6], w7 = s_w[ci][co][7], w8 = s_w[ci][co][8];
                #pragma unroll
                for (int i2 = 0; i2 < 2; i2++)
                    #pragma unroll
                    for (int j2 = 0; j2 < 2; j2++) {
                        float a = acc[co][i2][j2];
                        a += v[i2+0][j2+0] * w0;
                        a += v[i2+0][j2+1] * w1;
                        a += v[i2+0][j2+2] * w2;
                        a += v[i2+1][j2+0] * w3;
                        a += v[i2+1][j2+1] * w4;
                        a += v[i2+1][j2+2] * w5;
                        a += v[i2+2][j2+0] * w6;
                        a += v[i2+2][j2+1] * w7;
                        a += v[i2+2][j2+2] * w8;
                        acc[co][i2][j2] = a;
                    }
            }
        }
        __syncthreads();
    }

    #pragma unroll
    for (int co = 0; co < COT; co++) {
        int cog = co0 + co;
        if (cog >= Cout) break;
        float bv = bias[cog];
        #pragma unroll
        for (int i2 = 0; i2 < 2; i2++)
            #pragma unroll
            for (int j2 = 0; j2 < 2; j2++) {
                int oy = y0 + ty * 2 + i2, ox = x0 + tx * 2 + j2;
                float v = acc[co][i2][j2] + bv;
                if (act == ACT_GELU) v = gelu_f(v);
                else if (act == ACT_SIGM) v = sigmoid_f(v);
                out[((size_t)(bb * Cout + cog) * HW + oy) * HW + ox] = v;
            }
    }
}

// ---------------- fused flow-refiner chain ----------------
#define FR_OFF_W1 0
#define FR_OFF_B1 288
#define FR_OFF_W2 304
#define FR_OFF_B2 2608
#define FR_OFF_W3 2624
#define FR_OFF_B3 2912
#define FR_OFF_FI 2916
#define FR_OFF_T1 3884
#define FR_OFF_T2 10284
#define FR_SMEM_FLOATS 15468
#define FR_SMEM_BYTES (FR_SMEM_FLOATS * 4)

__global__ __launch_bounds__(256) void fr_fused_kernel(
    const float* __restrict__ fi,
    const float* __restrict__ w1, const float* __restrict__ b1,
    const float* __restrict__ w2, const float* __restrict__ b2,
    const float* __restrict__ w3, const float* __restrict__ b3,
    float* __restrict__ flow)
{
    extern __shared__ float sm[];
    const int tid = threadIdx.x;
    const int x0 = blockIdx.x * 16, y0 = blockIdx.y * 16;
    const int b = blockIdx.z;

    for (int u = tid; u < 288;  u += 256) sm[FR_OFF_W1 + u] = w1[u];
    for (int u = tid; u < 16;   u += 256) sm[FR_OFF_B1 + u] = b1[u];
    for (int u = tid; u < 2304; u += 256) sm[FR_OFF_W2 + u] = w2[u];
    for (int u = tid; u < 16;   u += 256) sm[FR_OFF_B2 + u] = b2[u];
    for (int u = tid; u < 288;  u += 256) sm[FR_OFF_W3 + u] = w3[u];
    for (int u = tid; u < 2;    u += 256) sm[FR_OFF_B3 + u] = b3[u];
    for (int u = tid; u < 2 * 484; u += 256) {
        int ci = u / 484;
        int rem = u % 484;
        int r = rem / 22, c = rem % 22;
        int gy = y0 - 3 + r, gx = x0 - 3 + c;
        float v = 0.f;
        if ((unsigned)gy < (unsigned)HW && (unsigned)gx < (unsigned)HW)
            v = fi[(size_t)(b * 2 + ci) * NPIX + gy * HW + gx];
        sm[FR_OFF_FI + u] = v;
    }
    __syncthreads();

    for (int u = tid; u < 16 * 400; u += 256) {
        int co = u / 400;
        int rem = u % 400;
        int r = rem / 20, c = rem % 20;
        int gy = y0 - 2 + r, gx = x0 - 2 + c;
        float v = 0.f;
        if ((unsigned)gy < (unsigned)HW && (unsigned)gx < (unsigned)HW) {
            float s = sm[FR_OFF_B1 + co];
            #pragma unroll
            for (int ci = 0; ci < 2; ci++)
                #pragma unroll
                for (int dy = 0; dy < 3; dy++)
                    #pragma unroll
                    for (int dx = 0; dx < 3; dx++)
                        s += sm[FR_OFF_FI + (ci * 22 + r + dy) * 22 + c + dx]
                           * sm[FR_OFF_W1 + (co * 2 + ci) * 9 + dy * 3 + dx];
            v = gelu_f(s);
        }
        sm[FR_OFF_T1 + u] = v;
    }
    __syncthreads();

    for (int u = tid; u < 16 * 324; u += 256) {
        int co = u / 324;
        int rem = u % 324;
        int r = rem / 18, c = rem % 18;
        int gy = y0 - 1 + r, gx = x0 - 1 + c;
        float v = 0.f;
        if ((unsigned)gy < (unsigned)HW && (unsigned)gx < (unsigned)HW) {
            float s = sm[FR_OFF_B2 + co];
            #pragma unroll
            for (int ci = 0; ci < 16; ci++) {
                const float* t1p = &sm[FR_OFF_T1 + (ci * 20 + r) * 20 + c];
                const float* wp  = &sm[FR_OFF_W2 + (co * 16 + ci) * 9];
                s += t1p[0]  * wp[0] + t1p[1]  * wp[1] + t1p[2]  * wp[2];
                s += t1p[20] * wp[3] + t1p[21] * wp[4] + t1p[22] * wp[5];
                s += t1p[40] * wp[6] + t1p[41] * wp[7] + t1p[42] * wp[8];
            }
            v = gelu_f(s);
        }
        sm[FR_OFF_T2 + u] = v;
    }
    __syncthreads();

    for (int u = tid; u < 2 * 256; u += 256) {
        int f = u / 256;
        int rem = u % 256;
        int r = rem / 16, c = rem % 16;
        float s = sm[FR_OFF_B3 + f];
        #pragma unroll
        for (int ci = 0; ci < 16; ci++) {
            const float* t2p = &sm[FR_OFF_T2 + (ci * 18 + r) * 18 + c];
            const float* wp  = &sm[FR_OFF_W3 + (f * 16 + ci) * 9];
            s += t2p[0]  * wp[0] + t2p[1]  * wp[1] + t2p[2]  * wp[2];
            s += t2p[18] * wp[3] + t2p[19] * wp[4] + t2p[20] * wp[5];
            s += t2p[36] * wp[6] + t2p[37] * wp[7] + t2p[38] * wp[8];
        }
        int gy = y0 + r, gx = x0 + c;
        flow[(size_t)(b * 2 + f) * NPIX + gy * HW + gx] += s;
    }
}

// ---------------- warp + diff + L2-normalize (lf NCHW) ----------------
__global__ __launch_bounds__(128) void warp_diff_kernel(
    const float* __restrict__ lf0, const float* __restrict__ lf1,
    const float* __restrict__ flow, float* __restrict__ xout)
{
    __shared__ float s_diff[64][129];
    __shared__ float s_ssq[128];
    __shared__ float s_rinv[64];

    const int tid = threadIdx.x;
    const int b = blockIdx.y;
    const int y = blockIdx.x >> 1;
    const int xbase = (blockIdx.x & 1) * 64;
    const int px = tid & 63;
    const int half = tid >> 6;
    const int x = xbase + px;

    float fx = flow[(b * 2 + 0) * NPIX + y * HW + x];
    float fy = flow[(b * 2 + 1) * NPIX + y * HW + x];
    float xs = fminf(fmaxf((float)x + fx, 0.f), 127.f);
    float ys = fminf(fmaxf((float)y + fy, 0.f), 127.f);
    float x0f = floorf(xs), y0f = floorf(ys);
    int ix0 = (int)x0f, iy0 = (int)y0f;
    int ix1 = min(ix0 + 1, 127), iy1 = min(iy0 + 1, 127);
    float wx = xs - x0f, wy = ys - y0f;
    float w00 = (1.f - wx) * (1.f - wy), w01 = wx * (1.f - wy);
    float w10 = (1.f - wx) * wy,         w11 = wx * wy;
    int o00 = iy0 * HW + ix0, o01 = iy0 * HW + ix1;
    int o10 = iy1 * HW + ix0, o11 = iy1 * HW + ix1;

    const float* lf1b = lf1 + (size_t)b * CH * NPIX;
    const float* lf0b = lf0 + (size_t)b * CH * NPIX;
    const int here = y * HW + x;

    float ssq = 0.f;
    for (int c = half * 64; c < half * 64 + 64; ++c) {
        const float* p = lf1b + (size_t)c * NPIX;
        float wv = w00 * p[o00] + w01 * p[o01] + w10 * p[o10] + w11 * p[o11];
        float d = lf0b[(size_t)c * NPIX + here] - wv;
        s_diff[px][c] = d;
        ssq += d * d;
    }
    s_ssq[tid] = ssq;
    __syncthreads();
    if (tid < 64) {
        float s = s_ssq[tid] + s_ssq[tid + 64];
        s_rinv[tid] = 1.f / fmaxf(sqrtf(s), 1e-12f);
    }
    __syncthreads();

    float* xb = xout + ((size_t)b * NPIX + y * HW + xbase) * CH;
    for (int p2 = 0; p2 < 64; ++p2)
        xb[(size_t)p2 * CH + tid] = 1.f - s_diff[p2][tid] * s_rinv[p2];
}

// ---------------- 25-tap local attention ----------------
__global__ __launch_bounds__(256) void attn_kernel(
    const float* __restrict__ Q, const float* __restrict__ K,
    const float* __restrict__ flow, float* __restrict__ fi)
{
    const int lane = threadIdx.x & 31;
    const int warp = threadIdx.x >> 5;
    const int p = blockIdx.x * 8 + warp;
    const int b = p >> 14;
    const int yx = p & 16383;
    const int y = yx >> 7, x = yx & 127;

    const float* qv = Q + (size_t)p * 128;
    const float q0 = qv[lane], q1 = qv[lane + 32], q2 = qv[lane + 64], q3 = qv[lane + 96];

    float s[25];
    #pragma unroll
    for (int t = 0; t < 25; t++) {
        const int dy = t / 5 - 2, dx = t % 5 - 2;
        const int ny = y + dy, nx = x + dx;
        float partial = 0.f;
        if ((unsigned)ny < (unsigned)HW && (unsigned)nx < (unsigned)HW) {
            const float* kv = K + ((size_t)(b << 14) + ny * HW + nx) * 128;
            partial = q0 * kv[lane] + q1 * kv[lane + 32] + q2 * kv[lane + 64] + q3 * kv[lane + 96];
        }
        #pragma unroll
        for (int off = 16; off; off >>= 1)
            partial += __shfl_xor_sync(0xffffffffu, partial, off);
        s[t] = partial * 0.08838834764831845f;
    }

    float mx = s[0];
    #pragma unroll
    for (int t = 1; t < 25; t++) mx = fmaxf(mx, s[t]);
    float sum = 0.f;
    #pragma unroll
    for (int t = 0; t < 25; t++) sum += expf(s[t] - mx);

    float c0 = 0.f, c1 = 0.f;
    if (lane < 25) {
        const int dy = lane / 5 - 2, dx = lane % 5 - 2;
        const int ny = y + dy, nx = x + dx;
        if ((unsigned)ny < (unsigned)HW && (unsigned)nx < (unsigned)HW) {
            const float w = expf(s[lane] - mx) / sum;
            c0 = w * flow[(size_t)(b * 2 + 0) * NPIX + ny * HW + nx];
            c1 = w * flow[(size_t)(b * 2 + 1) * NPIX + ny * HW + nx];
        }
    }
    #pragma unroll
    for (int off = 16; off; off >>= 1) {
        c0 += __shfl_xor_sync(0xffffffffu, c0, off);
        c1 += __shfl_xor_sync(0xffffffffu, c1, off);
    }
    if (lane == 0) {
        fi[(size_t)(b * 2 + 0) * NPIX + y * HW + x] = c0;
        fi[(size_t)(b * 2 + 1) * NPIX + y * HW + x] = c1;
    }
}

// ---------------- small utility kernels ----------------
__global__ void copy_kernel(float* __restrict__ dst, const float* __restrict__ src, int n) {
    int i = blockIdx.x * 256 + threadIdx.x;
    if (i < n) dst[i] = src[i];
}

// pack hcat = [feat0 | warp(feat1, flow) | flow | zeros] NHWC with stride CSH
__global__ __launch_bounds__(128) void pack_kernel(
    const float* __restrict__ feat0, const float* __restrict__ feat1,
    const float* __restrict__ flow, float* __restrict__ hcat)
{
    const int x = threadIdx.x;
    const int y = blockIdx.x;
    const int b = blockIdx.y;
    const int here = y * HW + x;

    float fx = flow[(b * 2 + 0) * NPIX + here];
    float fy = flow[(b * 2 + 1) * NPIX + here];
    float xs = fminf(fmaxf((float)x + fx, 0.f), 127.f);
    float ys = fminf(fmaxf((float)y + fy, 0.f), 127.f);
    float x0f = floorf(xs), y0f = floorf(ys);
    int ix0 = (int)x0f, iy0 = (int)y0f;
    int ix1 = min(ix0 + 1, 127), iy1 = min(iy0 + 1, 127);
    float wx = xs - x0f, wy = ys - y0f;
    float w00 = (1.f - wx) * (1.f - wy), w01 = wx * (1.f - wy);
    float w10 = (1.f - wx) * wy,         w11 = wx * wy;
    int o00 = iy0 * HW + ix0, o01 = iy0 * HW + ix1;
    int o10 = iy1 * HW + ix0, o11 = iy1 * HW + ix1;

    float* hb = hcat + ((size_t)b * NPIX + here) * CSH;
    const float* f0 = feat0 + (size_t)b * CH * NPIX;
    const float* f1 = feat1 + (size_t)b * CH * NPIX;

    for (int c = 0; c < CH; c++) {
        hb[c] = f0[(size_t)c * NPIX + here];
        const float* p = f1 + (size_t)c * NPIX;
        hb[CH + c] = w00 * p[o00] + w01 * p[o01] + w10 * p[o10] + w11 * p[o11];
    }
    hb[256] = fx;
    hb[257] = fy;
    for (int c = 258; c < CSH; c++) hb[c] = 0.f;
}

// ---------------- host orchestration ----------------
static float* sym_addr(const void* symbol) {
    void* p = nullptr;
    cudaGetSymbolAddress(&p, symbol);
    return (float*)p;
}

extern "C" void kernel_launch(void* const* d_in, const int* in_sizes, int n_in,
                              void* d_out, int out_size)
{
    (void)in_sizes; (void)n_in; (void)out_size;
    const float* feat0     = (const float*)d_in[0];
    const float* feat1     = (const float*)d_in[1];
    const float* flow_init = (const float*)d_in[2];
    const float* lc_w1 = (const float*)d_in[3];
    const float* lc_b1 = (const float*)d_in[4];
    const float* lc_w2 = (const float*)d_in[5];
    const float* lc_b2 = (const float*)d_in[6];
    const float* qw    = (const float*)d_in[7];
    const float* qb    = (const float*)d_in[8];
    const float* kw    = (const float*)d_in[9];
    const float* kb    = (const float*)d_in[10];
    const float* fr_w1 = (const float*)d_in[11];
    const float* fr_b1 = (const float*)d_in[12];
    const float* fr_w2 = (const float*)d_in[13];
    const float* fr_b2 = (const float*)d_in[14];
    const float* fr_w3 = (const float*)d_in[15];
    const float* fr_b3 = (const float*)d_in[16];
    const float* cf_w1 = (const float*)d_in[17];
    const float* cf_b1 = (const float*)d_in[18];
    const float* cf_w2 = (const float*)d_in[19];
    const float* cf_b2 = (const float*)d_in[20];
    const float* cf_w3 = (const float*)d_in[21];
    const float* cf_b3 = (const float*)d_in[22];

    float* lf0  = sym_addr(g_lf0);
    float* lf1  = sym_addr(g_lf1);
    float* nA   = sym_addr(g_nA);
    float* nB   = sym_addr(g_nB);
    float* xbuf = sym_addr(g_x);
    float* qbuf = sym_addr(g_q);
    float* kbuf = sym_addr(g_k);
    float* flow = sym_addr(g_flow);
    float* fi   = sym_addr(g_fi);
    float* hcat = sym_addr(g_hcat);
    float* h2   = sym_addr(g_h2);
    float* wt1  = sym_addr(g_wt1);
    float* wt2  = sym_addr(g_wt2);
    float* wtc1 = sym_addr(g_wtc1);
    float* wtc2 = sym_addr(g_wtc2);
    float* out_flow = (float*)d_out;
    float* out_conf = (float*)d_out + BATCH * 2 * NPIX;

    cudaFuncSetAttribute(fr_fused_kernel,
                         cudaFuncAttributeMaxDynamicSharedMemorySize, FR_SMEM_BYTES);
    cudaFuncSetAttribute(conv3x3_tc_kernel,
                         cudaFuncAttributeMaxDynamicSharedMemorySize, CONV_SMEM_BYTES);
    cudaFuncSetAttribute(gemm_qk_tc_kernel,
                         cudaFuncAttributeMaxDynamicSharedMemorySize, QK_SMEM_BYTES);

    // weight transposes
    wtrans_kernel<<<(9*CH*CH + 255)/256, 256>>>(lc_w1, wt1, CH, CH, CH);
    wtrans_kernel<<<(9*CH*CH + 255)/256, 256>>>(lc_w2, wt2, CH, CH, CH);
    wtrans_kernel<<<(9*CSH*CH + 255)/256, 256>>>(cf_w1, wtc1, 258, CSH, CH);
    wtrans_kernel<<<(9*CH*64 + 255)/256, 256>>>(cf_w2, wtc2, CH, CH, 64);

    // local_conv on both features (hoisted)
    nchw2nhwc_kernel<<<dim3(NPIX/32, 4, BATCH), 256>>>(feat0, nA);
    conv3x3_tc_kernel<<<dim3(2, HW, BATCH), 256, CONV_SMEM_BYTES>>>(
        nA, wt1, lc_b1, nB, CH, CH, CH, CH, ACT_GELU, LAYOUT_NHWC);
    conv3x3_tc_kernel<<<dim3(2, HW, BATCH), 256, CONV_SMEM_BYTES>>>(
        nB, wt2, lc_b2, lf0, CH, CH, CH, CH, ACT_NONE, LAYOUT_NCHW);
    nchw2nhwc_kernel<<<dim3(NPIX/32, 4, BATCH), 256>>>(feat1, nA);
    conv3x3_tc_kernel<<<dim3(2, HW, BATCH), 256, CONV_SMEM_BYTES>>>(
        nA, wt1, lc_b1, nB, CH, CH, CH, CH, ACT_GELU, LAYOUT_NHWC);
    conv3x3_tc_kernel<<<dim3(2, HW, BATCH), 256, CONV_SMEM_BYTES>>>(
        nB, wt2, lc_b2, lf1, CH, CH, CH, CH, ACT_NONE, LAYOUT_NCHW);

    copy_kernel<<<(BATCH*2*NPIX + 255)/256, 256>>>(flow, flow_init, BATCH*2*NPIX);

    for (int it = 0; it < ITERS; ++it) {
        warp_diff_kernel<<<dim3(2*HW, BATCH), 128>>>(lf0, lf1, flow, xbuf);
        gemm_qk_tc_kernel<<<dim3(BATCH*NPIX/128, 2), 256, QK_SMEM_BYTES>>>(
            xbuf, qw, qb, kw, kb, qbuf, kbuf);
        attn_kernel<<<BATCH*NPIX/8, 256>>>(qbuf, kbuf, flow, fi);
        fr_fused_kernel<<<dim3(8,8,BATCH), 256, FR_SMEM_BYTES>>>(
            fi, fr_w1, fr_b1, fr_w2, fr_b2, fr_w3, fr_b3, flow);
    }

    // confidence head
    pack_kernel<<<dim3(HW, BATCH), 128>>>(feat0, feat1, flow, hcat);
    conv3x3_tc_kernel<<<dim3(2, HW, BATCH), 256, CONV_SMEM_BYTES>>>(
        hcat, wtc1, cf_b1, nB, CSH, CSH, CH, CH, ACT_GELU, LAYOUT_NHWC);
    conv3x3_tc_kernel<<<dim3(1, HW, BATCH), 256, CONV_SMEM_BYTES>>>(
        nB, wtc2, cf_b2, h2, CH, CH, 64, 64, ACT_GELU, LAYOUT_NCHW);
    conv3x3_kernel<2><<<dim3(4,4,BATCH), 256>>>(h2, cf_w3, cf_b3, out_conf, 64, 1, ACT_SIGM);

    copy_kernel<<<(BATCH*2*NPIX + 255)/256, 256>>>(out_flow, flow, BATCH*2*NPIX);
}

// round 6
// speedup vs baseline: 1.5549x; 1.5549x over previous
#include <cuda_runtime.h>
#include <stdint.h>
#include <math.h>

#define HW     128
#define BATCH  2
#define CH     128
#define NPIX   (HW*HW)            // 16384
#define ITERS  10

// ---------------- scratch (static device allocations; no cudaMalloc) ----------------
__device__ float g_lf0 [BATCH*CH*NPIX];
__device__ float g_lf1 [BATCH*CH*NPIX];
__device__ float g_tmp [BATCH*CH*NPIX];      // conv intermediate / h1
__device__ float g_x   [BATCH*NPIX*CH];      // channel-last attention input
__device__ float g_y   [BATCH*NPIX*CH];      // y = M x (channel-last)
__device__ float g_flow[BATCH*2*NPIX];
__device__ float g_fi  [BATCH*2*NPIX];
__device__ float g_hcat[BATCH*258*NPIX];
__device__ float g_h2  [BATCH*64*NPIX];
__device__ float g_M   [CH*CH];              // Wq^T Wk
__device__ float g_u   [CH];                 // Wq^T kb
__device__ float g_bv  [CH];                 // Wk^T qb
__device__ float g_c   [1];                  // qb . kb
__device__ float g_bscal[BATCH*NPIX];        // bv . x per pixel

// ---------------- helpers ----------------
__device__ __forceinline__ float gelu_f(float v) {
    return 0.5f * v * (1.0f + erff(v * 0.70710678118654752f));
}
__device__ __forceinline__ float sigmoid_f(float v) {
    return 1.0f / (1.0f + expf(-v));
}
__device__ __forceinline__ void cp_async4(float* dst, const float* src, bool ok) {
    unsigned int d = (unsigned int)__cvta_generic_to_shared(dst);
    int sz = ok ? 4 : 0;
    asm volatile("cp.async.ca.shared.global [%0], [%1], 4, %2;\n"
                 :: "r"(d), "l"(src), "r"(sz));
}

#define ACT_NONE 0
#define ACT_GELU 1
#define ACT_SIGM 2

// ---------------- prep: M = Wq^T Wk ; u = Wq^T kb ; bv = Wk^T qb ; c = qb.kb ----------------
__global__ void prepM_kernel(const float* __restrict__ qw, const float* __restrict__ kw,
                             float* __restrict__ M)
{
    int i = blockIdx.x, j = threadIdx.x;
    float s = 0.f;
    for (int d = 0; d < CH; d++)
        s += qw[d * CH + i] * kw[d * CH + j];
    M[i * CH + j] = s;
}

__global__ void prepUV_kernel(const float* __restrict__ qw, const float* __restrict__ kw,
                              const float* __restrict__ qb, const float* __restrict__ kb,
                              float* __restrict__ u, float* __restrict__ bv, float* __restrict__ c)
{
    int j = threadIdx.x;
    float su = 0.f, sb = 0.f;
    for (int d = 0; d < CH; d++) {
        su += qw[d * CH + j] * kb[d];
        sb += kw[d * CH + j] * qb[d];
    }
    u[j] = su;
    bv[j] = sb;
    if (j == 0) {
        float cc = 0.f;
        for (int d = 0; d < CH; d++) cc += qb[d] * kb[d];
        c[0] = cc;
    }
}

// ---------------- double-buffered NCHW 3x3 conv (cp.async pipelined) ----------------
// block 256 (16x16), 2x2 px/thread (32x32 tile), COT couts/block, 4-cin slices ping-pong.
template<int COT>
__global__ __launch_bounds__(256, 2) void conv3x3_db_kernel(
    const float* __restrict__ in, const float* __restrict__ wgt,
    const float* __restrict__ bias, float* __restrict__ out,
    int Cin, int Cout, int act)
{
    __shared__ float s_in[2][4][34][34];
    __shared__ float s_w[2][4][COT][9];

    const int tid = threadIdx.x;
    const int tx = tid & 15, ty = tid >> 4;
    const int x0 = blockIdx.x * 32, y0 = blockIdx.y * 32;
    const int nco = (Cout + COT - 1) / COT;
    const int bb  = blockIdx.z / nco;
    const int co0 = (blockIdx.z % nco) * COT;

    float acc[COT][2][2];
    #pragma unroll
    for (int c = 0; c < COT; c++)
        #pragma unroll
        for (int i = 0; i < 2; i++)
            #pragma unroll
            for (int j = 0; j < 2; j++) acc[c][i][j] = 0.f;

    const int nsl = (Cin + 3) >> 2;

    // stage slice `sl` into buffer `s`
    auto stage = [&](int s, int sl) {
        const int c0 = sl * 4;
        for (int idx = tid; idx < 4 * 1156; idx += 256) {
            int ci = idx / 1156;
            int rem = idx % 1156;
            int r  = rem / 34;
            int cc = rem % 34;
            int gy = y0 - 1 + r, gx = x0 - 1 + cc;
            int cin = c0 + ci;
            bool ok = (cin < Cin) && ((unsigned)gy < (unsigned)HW) && ((unsigned)gx < (unsigned)HW);
            const float* src = ok ? &in[((size_t)(bb * Cin + cin) * HW + gy) * HW + gx] : in;
            cp_async4(&s_in[s][ci][r][cc], src, ok);
        }
        for (int idx = tid; idx < 4 * COT * 9; idx += 256) {
            int ci = idx / (COT * 9);
            int co = (idx % (COT * 9)) / 9;
            int k  = idx % 9;
            int cin = c0 + ci, cog = co0 + co;
            float v = 0.f;
            if (cin < Cin && cog < Cout)
                v = wgt[((size_t)cog * Cin + cin) * 9 + k];
            s_w[s][ci][co][k] = v;
        }
        asm volatile("cp.async.commit_group;\n" ::: "memory");
    };

    stage(0, 0);

    for (int cs = 0; cs < nsl; cs++) {
        if (cs + 1 < nsl) {
            stage((cs + 1) & 1, cs + 1);
            asm volatile("cp.async.wait_group 1;\n" ::: "memory");
        } else {
            asm volatile("cp.async.wait_group 0;\n" ::: "memory");
        }
        __syncthreads();   // slice cs data + weights visible

        const int cur = cs & 1;
        #pragma unroll
        for (int ci = 0; ci < 4; ci++) {
            float v[4][4];
            #pragma unroll
            for (int i = 0; i < 4; i++)
                #pragma unroll
                for (int j = 0; j < 4; j++)
                    v[i][j] = s_in[cur][ci][ty * 2 + i][tx * 2 + j];
            #pragma unroll
            for (int co = 0; co < COT; co++) {
                float w0 = s_w[cur][ci][co][0], w1 = s_w[cur][ci][co][1], w2 = s_w[cur][ci][co][2];
                float w3 = s_w[cur][ci][co][3], w4 = s_w[cur][ci][co][4], w5 = s_w[cur][ci][co][5];
                float w6 = s_w[cur][ci][co][6], w7 = s_w[cur][ci][co][7], w8 = s_w[cur][ci][co][8];
                #pragma unroll
                for (int i2 = 0; i2 < 2; i2++)
                    #pragma unroll
                    for (int j2 = 0; j2 < 2; j2++) {
                        float a = acc[co][i2][j2];
                        a += v[i2+0][j2+0] * w0;
                        a += v[i2+0][j2+1] * w1;
                        a += v[i2+0][j2+2] * w2;
                        a += v[i2+1][j2+0] * w3;
                        a += v[i2+1][j2+1] * w4;
                        a += v[i2+1][j2+2] * w5;
                        a += v[i2+2][j2+0] * w6;
                        a += v[i2+2][j2+1] * w7;
                        a += v[i2+2][j2+2] * w8;
                        acc[co][i2][j2] = a;
                    }
            }
        }
        __syncthreads();   // all warps done with buf cur before it is re-staged
    }

    #pragma unroll
    for (int co = 0; co < COT; co++) {
        int cog = co0 + co;
        if (cog >= Cout) break;
        float bv = bias[cog];
        #pragma unroll
        for (int i2 = 0; i2 < 2; i2++)
            #pragma unroll
            for (int j2 = 0; j2 < 2; j2++) {
                int oy = y0 + ty * 2 + i2, ox = x0 + tx * 2 + j2;
                float v = acc[co][i2][j2] + bv;
                if (act == ACT_GELU) v = gelu_f(v);
                else if (act == ACT_SIGM) v = sigmoid_f(v);
                out[((size_t)(bb * Cout + cog) * HW + oy) * HW + ox] = v;
            }
    }
}

// ---------------- plain conv (tiny cf3: 64 -> 1) ----------------
template<int COT>
__global__ __launch_bounds__(256, 2) void conv3x3_kernel(
    const float* __restrict__ in, const float* __restrict__ wgt,
    const float* __restrict__ bias, float* __restrict__ out,
    int Cin, int Cout, int act)
{
    __shared__ float s_in[8][34][34];
    __shared__ float s_w[8][COT][9];

    const int tid = threadIdx.x;
    const int tx = tid & 15, ty = tid >> 4;
    const int x0 = blockIdx.x * 32, y0 = blockIdx.y * 32;
    const int nco = (Cout + COT - 1) / COT;
    const int bb  = blockIdx.z / nco;
    const int co0 = (blockIdx.z % nco) * COT;

    float acc[COT][2][2];
    #pragma unroll
    for (int c = 0; c < COT; c++)
        #pragma unroll
        for (int i = 0; i < 2; i++)
            #pragma unroll
            for (int j = 0; j < 2; j++) acc[c][i][j] = 0.f;

    for (int c0 = 0; c0 < Cin; c0 += 8) {
        for (int idx = tid; idx < 8 * 1156; idx += 256) {
            int ci = idx / 1156;
            int r  = (idx % 1156) / 34;
            int cc = idx % 34;
            int gy = y0 - 1 + r, gx = x0 - 1 + cc;
            int cin = c0 + ci;
            float v = 0.f;
            if (cin < Cin && (unsigned)gy < (unsigned)HW && (unsigned)gx < (unsigned)HW)
                v = in[((size_t)(bb * Cin + cin) * HW + gy) * HW + gx];
            s_in[ci][r][cc] = v;
        }
        for (int idx = tid; idx < 8 * COT * 9; idx += 256) {
            int ci = idx / (COT * 9);
            int co = (idx % (COT * 9)) / 9;
            int k  = idx % 9;
            int cin = c0 + ci, cog = co0 + co;
            float v = 0.f;
            if (cin < Cin && cog < Cout)
                v = wgt[((size_t)cog * Cin + cin) * 9 + k];
            s_w[ci][co][k] = v;
        }
        __syncthreads();

        #pragma unroll
        for (int ci = 0; ci < 8; ci++) {
            float v[4][4];
            #pragma unroll
            for (int i = 0; i < 4; i++)
                #pragma unroll
                for (int j = 0; j < 4; j++)
                    v[i][j] = s_in[ci][ty * 2 + i][tx * 2 + j];
            #pragma unroll
            for (int co = 0; co < COT; co++) {
                float w0 = s_w[ci][co][0], w1 = s_w[ci][co][1], w2 = s_w[ci][co][2];
                float w3 = s_w[ci][co][3], w4 = s_w[ci][co][4], w5 = s_w[ci][co][5];
                float w6 = s_w[ci][co][6], w7 = s_w[ci][co][7], w8 = s_w[ci][co][8];
                #pragma unroll
                for (int i2 = 0; i2 < 2; i2++)
                    #pragma unroll
                    for (int j2 = 0; j2 < 2; j2++) {
                        float a = acc[co][i2][j2];
                        a += v[i2+0][j2+0] * w0;
                        a += v[i2+0][j2+1] * w1;
                        a += v[i2+0][j2+2] * w2;
                        a += v[i2+1][j2+0] * w3;
                        a += v[i2+1][j2+1] * w4;
                        a += v[i2+1][j2+2] * w5;
                        a += v[i2+2][j2+0] * w6;
                        a += v[i2+2][j2+1] * w7;
                        a += v[i2+2][j2+2] * w8;
                        acc[co][i2][j2] = a;
                    }
            }
        }
        __syncthreads();
    }

    #pragma unroll
    for (int co = 0; co < COT; co++) {
        int cog = co0 + co;
        if (cog >= Cout) break;
        float bv = bias[cog];
        #pragma unroll
        for (int i2 = 0; i2 < 2; i2++)
            #pragma unroll
            for (int j2 = 0; j2 < 2; j2++) {
                int oy = y0 + ty * 2 + i2, ox = x0 + tx * 2 + j2;
                float v = acc[co][i2][j2] + bv;
                if (act == ACT_GELU) v = gelu_f(v);
                else if (act == ACT_SIGM) v = sigmoid_f(v);
                out[((size_t)(bb * Cout + cog) * HW + oy) * HW + ox] = v;
            }
    }
}

// ---------------- fused flow-refiner chain ----------------
#define FR_OFF_W1 0
#define FR_OFF_B1 288
#define FR_OFF_W2 304
#define FR_OFF_B2 2608
#define FR_OFF_W3 2624
#define FR_OFF_B3 2912
#define FR_OFF_FI 2916
#define FR_OFF_T1 3884
#define FR_OFF_T2 10284
#define FR_SMEM_FLOATS 15468
#define FR_SMEM_BYTES (FR_SMEM_FLOATS * 4)

__global__ __launch_bounds__(256) void fr_fused_kernel(
    const float* __restrict__ fi,
    const float* __restrict__ w1, const float* __restrict__ b1,
    const float* __restrict__ w2, const float* __restrict__ b2,
    const float* __restrict__ w3, const float* __restrict__ b3,
    float* __restrict__ flow)
{
    extern __shared__ float sm[];
    const int tid = threadIdx.x;
    const int x0 = blockIdx.x * 16, y0 = blockIdx.y * 16;
    const int b = blockIdx.z;

    for (int u = tid; u < 288;  u += 256) sm[FR_OFF_W1 + u] = w1[u];
    for (int u = tid; u < 16;   u += 256) sm[FR_OFF_B1 + u] = b1[u];
    for (int u = tid; u < 2304; u += 256) sm[FR_OFF_W2 + u] = w2[u];
    for (int u = tid; u < 16;   u += 256) sm[FR_OFF_B2 + u] = b2[u];
    for (int u = tid; u < 288;  u += 256) sm[FR_OFF_W3 + u] = w3[u];
    for (int u = tid; u < 2;    u += 256) sm[FR_OFF_B3 + u] = b3[u];
    for (int u = tid; u < 2 * 484; u += 256) {
        int ci = u / 484;
        int rem = u % 484;
        int r = rem / 22, c = rem % 22;
        int gy = y0 - 3 + r, gx = x0 - 3 + c;
        float v = 0.f;
        if ((unsigned)gy < (unsigned)HW && (unsigned)gx < (unsigned)HW)
            v = fi[(size_t)(b * 2 + ci) * NPIX + gy * HW + gx];
        sm[FR_OFF_FI + u] = v;
    }
    __syncthreads();

    for (int u = tid; u < 16 * 400; u += 256) {
        int co = u / 400;
        int rem = u % 400;
        int r = rem / 20, c = rem % 20;
        int gy = y0 - 2 + r, gx = x0 - 2 + c;
        float v = 0.f;
        if ((unsigned)gy < (unsigned)HW && (unsigned)gx < (unsigned)HW) {
            float s = sm[FR_OFF_B1 + co];
            #pragma unroll
            for (int ci = 0; ci < 2; ci++)
                #pragma unroll
                for (int dy = 0; dy < 3; dy++)
                    #pragma unroll
                    for (int dx = 0; dx < 3; dx++)
                        s += sm[FR_OFF_FI + (ci * 22 + r + dy) * 22 + c + dx]
                           * sm[FR_OFF_W1 + (co * 2 + ci) * 9 + dy * 3 + dx];
            v = gelu_f(s);
        }
        sm[FR_OFF_T1 + u] = v;
    }
    __syncthreads();

    for (int u = tid; u < 16 * 324; u += 256) {
        int co = u / 324;
        int rem = u % 324;
        int r = rem / 18, c = rem % 18;
        int gy = y0 - 1 + r, gx = x0 - 1 + c;
        float v = 0.f;
        if ((unsigned)gy < (unsigned)HW && (unsigned)gx < (unsigned)HW) {
            float s = sm[FR_OFF_B2 + co];
            #pragma unroll
            for (int ci = 0; ci < 16; ci++) {
                const float* t1p = &sm[FR_OFF_T1 + (ci * 20 + r) * 20 + c];
                const float* wp  = &sm[FR_OFF_W2 + (co * 16 + ci) * 9];
                s += t1p[0]  * wp[0] + t1p[1]  * wp[1] + t1p[2]  * wp[2];
                s += t1p[20] * wp[3] + t1p[21] * wp[4] + t1p[22] * wp[5];
                s += t1p[40] * wp[6] + t1p[41] * wp[7] + t1p[42] * wp[8];
            }
            v = gelu_f(s);
        }
        sm[FR_OFF_T2 + u] = v;
    }
    __syncthreads();

    for (int u = tid; u < 2 * 256; u += 256) {
        int f = u / 256;
        int rem = u % 256;
        int r = rem / 16, c = rem % 16;
        float s = sm[FR_OFF_B3 + f];
        #pragma unroll
        for (int ci = 0; ci < 16; ci++) {
            const float* t2p = &sm[FR_OFF_T2 + (ci * 18 + r) * 18 + c];
            const float* wp  = &sm[FR_OFF_W3 + (f * 16 + ci) * 9];
            s += t2p[0]  * wp[0] + t2p[1]  * wp[1] + t2p[2]  * wp[2];
            s += t2p[18] * wp[3] + t2p[19] * wp[4] + t2p[20] * wp[5];
            s += t2p[36] * wp[6] + t2p[37] * wp[7] + t2p[38] * wp[8];
        }
        int gy = y0 + r, gx = x0 + c;
        flow[(size_t)(b * 2 + f) * NPIX + gy * HW + gx] += s;
    }
}

// ---------------- warp + diff + L2-normalize; x = 1 - diffn channel-last ----------------
__global__ __launch_bounds__(128) void warp_diff_kernel(
    const float* __restrict__ lf0, const float* __restrict__ lf1,
    const float* __restrict__ flow, float* __restrict__ xout)
{
    __shared__ float s_diff[64][129];
    __shared__ float s_ssq[128];
    __shared__ float s_rinv[64];

    const int tid = threadIdx.x;
    const int b = blockIdx.y;
    const int y = blockIdx.x >> 1;
    const int xbase = (blockIdx.x & 1) * 64;
    const int px = tid & 63;
    const int half = tid >> 6;
    const int x = xbase + px;

    float fx = flow[(b * 2 + 0) * NPIX + y * HW + x];
    float fy = flow[(b * 2 + 1) * NPIX + y * HW + x];
    float xs = fminf(fmaxf((float)x + fx, 0.f), 127.f);
    float ys = fminf(fmaxf((float)y + fy, 0.f), 127.f);
    float x0f = floorf(xs), y0f = floorf(ys);
    int ix0 = (int)x0f, iy0 = (int)y0f;
    int ix1 = min(ix0 + 1, 127), iy1 = min(iy0 + 1, 127);
    float wx = xs - x0f, wy = ys - y0f;
    float w00 = (1.f - wx) * (1.f - wy), w01 = wx * (1.f - wy);
    float w10 = (1.f - wx) * wy,         w11 = wx * wy;
    int o00 = iy0 * HW + ix0, o01 = iy0 * HW + ix1;
    int o10 = iy1 * HW + ix0, o11 = iy1 * HW + ix1;

    const float* lf1b = lf1 + (size_t)b * CH * NPIX;
    const float* lf0b = lf0 + (size_t)b * CH * NPIX;
    const int here = y * HW + x;

    float ssq = 0.f;
    for (int c = half * 64; c < half * 64 + 64; ++c) {
        const float* p = lf1b + (size_t)c * NPIX;
        float wv = w00 * p[o00] + w01 * p[o01] + w10 * p[o10] + w11 * p[o11];
        float d = lf0b[(size_t)c * NPIX + here] - wv;
        s_diff[px][c] = d;
        ssq += d * d;
    }
    s_ssq[tid] = ssq;
    __syncthreads();
    if (tid < 64) {
        float s = s_ssq[tid] + s_ssq[tid + 64];
        s_rinv[tid] = 1.f / fmaxf(sqrtf(s), 1e-12f);
    }
    __syncthreads();

    float* xb = xout + ((size_t)b * NPIX + y * HW + xbase) * CH;
    for (int p2 = 0; p2 < 64; ++p2)
        xb[(size_t)p2 * CH + tid] = 1.f - s_diff[p2][tid] * s_rinv[p2];
}

// ---------------- y = M x : [32768,128] x M[128,128] (row i of M . x) + bscal = bv.x ----------------
__global__ __launch_bounds__(256) void gemm_y_kernel(
    const float* __restrict__ X, const float* __restrict__ M,
    const float* __restrict__ bv,
    float* __restrict__ Y, float* __restrict__ bscal)
{
    __shared__ float As[8][132];
    __shared__ float Bs[8][132];
    __shared__ float sbv[128];

    const int tid = threadIdx.x;
    const int tx = tid & 15, ty = tid >> 4;
    const int m0 = blockIdx.x * 128;

    if (tid < 128) sbv[tid] = bv[tid];
    __syncthreads();

    float acc[8][8];
    #pragma unroll
    for (int i = 0; i < 8; i++)
        #pragma unroll
        for (int j = 0; j < 8; j++) acc[i][j] = 0.f;

    const int row  = tid >> 1;   // 0..127
    const int part = tid & 1;
    float bdot = 0.f;

    for (int kk = 0; kk < 128; kk += 8) {
        float4 a = *(const float4*)&X[(size_t)(m0 + row) * 128 + kk + part * 4];
        float4 b = *(const float4*)&M[(size_t)row * 128 + kk + part * 4];
        int kb4 = kk + part * 4;
        bdot += a.x * sbv[kb4+0] + a.y * sbv[kb4+1] + a.z * sbv[kb4+2] + a.w * sbv[kb4+3];
        As[part*4+0][row] = a.x; As[part*4+1][row] = a.y;
        As[part*4+2][row] = a.z; As[part*4+3][row] = a.w;
        Bs[part*4+0][row] = b.x; Bs[part*4+1][row] = b.y;
        Bs[part*4+2][row] = b.z; Bs[part*4+3][row] = b.w;
        __syncthreads();
        #pragma unroll
        for (int k = 0; k < 8; k++) {
            float af[8], bf[8];
            *(float4*)&af[0] = *(const float4*)&As[k][ty * 8];
            *(float4*)&af[4] = *(const float4*)&As[k][ty * 8 + 4];
            *(float4*)&bf[0] = *(const float4*)&Bs[k][tx * 8];
            *(float4*)&bf[4] = *(const float4*)&Bs[k][tx * 8 + 4];
            #pragma unroll
            for (int i = 0; i < 8; i++)
                #pragma unroll
                for (int j = 0; j < 8; j++)
                    acc[i][j] += af[i] * bf[j];
        }
        __syncthreads();
    }

    // bscal: combine the two half-dots (adjacent lanes)
    float other = __shfl_xor_sync(0xffffffffu, bdot, 1);
    if (part == 0) bscal[m0 + row] = bdot + other;

    #pragma unroll
    for (int i = 0; i < 8; i++) {
        int m = m0 + ty * 8 + i;
        #pragma unroll
        for (int j = 0; j < 8; j++)
            Y[(size_t)m * 128 + tx * 8 + j] = acc[i][j];
    }
}

// ---------------- 25-tap local attention on (x, y=Mx) ----------------
// score_in = (x_p.y_n + b_n)/sqrt(C); score_oob = -(a_p + c)/sqrt(C)
// (uniform shift of the reference scores -> identical softmax)
__global__ __launch_bounds__(256) void attn_kernel(
    const float* __restrict__ X, const float* __restrict__ Y,
    const float* __restrict__ bscal, const float* __restrict__ uvec,
    const float* __restrict__ cconst,
    const float* __restrict__ flow, float* __restrict__ fi)
{
    const float SCALE = 0.08838834764831845f;   // 1/sqrt(128)
    const int lane = threadIdx.x & 31;
    const int warp = threadIdx.x >> 5;
    const int p = blockIdx.x * 8 + warp;     // 0..32767
    const int b = p >> 14;
    const int yx = p & 16383;
    const int y = yx >> 7, x = yx & 127;

    const float* xv = X + (size_t)p * 128;
    const float x0 = xv[lane], x1 = xv[lane + 32], x2 = xv[lane + 64], x3 = xv[lane + 96];

    // a_p = u . x_p
    float ap = x0 * uvec[lane] + x1 * uvec[lane + 32] + x2 * uvec[lane + 64] + x3 * uvec[lane + 96];
    #pragma unroll
    for (int off = 16; off; off >>= 1)
        ap += __shfl_xor_sync(0xffffffffu, ap, off);
    const float oobs = -(ap + cconst[0]) * SCALE;

    float s[25];
    #pragma unroll
    for (int t = 0; t < 25; t++) {
        const int dy = t / 5 - 2, dx = t % 5 - 2;
        const int ny = y + dy, nx = x + dx;
        if ((unsigned)ny < (unsigned)HW && (unsigned)nx < (unsigned)HW) {
            const int n = (b << 14) + ny * HW + nx;
            const float* yv = Y + (size_t)n * 128;
            float partial = x0 * yv[lane] + x1 * yv[lane + 32] + x2 * yv[lane + 64] + x3 * yv[lane + 96];
            #pragma unroll
            for (int off = 16; off; off >>= 1)
                partial += __shfl_xor_sync(0xffffffffu, partial, off);
            s[t] = (partial + bscal[n]) * SCALE;
        } else {
            s[t] = oobs;
        }
    }

    float mx = s[0];
    #pragma unroll
    for (int t = 1; t < 25; t++) mx = fmaxf(mx, s[t]);
    float sum = 0.f;
    #pragma unroll
    for (int t = 0; t < 25; t++) sum += expf(s[t] - mx);

    float c0 = 0.f, c1 = 0.f;
    if (lane < 25) {
        const int dy = lane / 5 - 2, dx = lane % 5 - 2;
        const int ny = y + dy, nx = x + dx;
        if ((unsigned)ny < (unsigned)HW && (unsigned)nx < (unsigned)HW) {
            const float w = expf(s[lane] - mx) / sum;
            c0 = w * flow[(size_t)(b * 2 + 0) * NPIX + ny * HW + nx];
            c1 = w * flow[(size_t)(b * 2 + 1) * NPIX + ny * HW + nx];
        }
    }
    #pragma unroll
    for (int off = 16; off; off >>= 1) {
        c0 += __shfl_xor_sync(0xffffffffu, c0, off);
        c1 += __shfl_xor_sync(0xffffffffu, c1, off);
    }
    if (lane == 0) {
        fi[(size_t)(b * 2 + 0) * NPIX + y * HW + x] = c0;
        fi[(size_t)(b * 2 + 1) * NPIX + y * HW + x] = c1;
    }
}

// ---------------- small utility kernels ----------------
__global__ void copy_kernel(float* __restrict__ dst, const float* __restrict__ src, int n) {
    int i = blockIdx.x * 256 + threadIdx.x;
    if (i < n) dst[i] = src[i];
}

// pack hcat = [feat0 | warp(feat1, flow) | flow] NCHW
__global__ __launch_bounds__(128) void pack_kernel(
    const float* __restrict__ feat0, const float* __restrict__ feat1,
    const float* __restrict__ flow, float* __restrict__ hcat)
{
    const int x = threadIdx.x;
    const int y = blockIdx.x;
    const int b = blockIdx.y;
    const int here = y * HW + x;

    float fx = flow[(b * 2 + 0) * NPIX + here];
    float fy = flow[(b * 2 + 1) * NPIX + here];
    float xs = fminf(fmaxf((float)x + fx, 0.f), 127.f);
    float ys = fminf(fmaxf((float)y + fy, 0.f), 127.f);
    float x0f = floorf(xs), y0f = floorf(ys);
    int ix0 = (int)x0f, iy0 = (int)y0f;
    int ix1 = min(ix0 + 1, 127), iy1 = min(iy0 + 1, 127);
    float wx = xs - x0f, wy = ys - y0f;
    float w00 = (1.f - wx) * (1.f - wy), w01 = wx * (1.f - wy);
    float w10 = (1.f - wx) * wy,         w11 = wx * wy;
    int o00 = iy0 * HW + ix0, o01 = iy0 * HW + ix1;
    int o10 = iy1 * HW + ix0, o11 = iy1 * HW + ix1;

    float* hb = hcat + (size_t)b * 258 * NPIX;
    const float* f0 = feat0 + (size_t)b * CH * NPIX;
    const float* f1 = feat1 + (size_t)b * CH * NPIX;

    for (int c = 0; c < CH; c++) {
        hb[(size_t)c * NPIX + here] = f0[(size_t)c * NPIX + here];
        const float* p = f1 + (size_t)c * NPIX;
        hb[(size_t)(CH + c) * NPIX + here] =
            w00 * p[o00] + w01 * p[o01] + w10 * p[o10] + w11 * p[o11];
    }
    hb[(size_t)256 * NPIX + here] = fx;
    hb[(size_t)257 * NPIX + here] = fy;
}

// ---------------- host orchestration ----------------
static float* sym_addr(const void* symbol) {
    void* p = nullptr;
    cudaGetSymbolAddress(&p, symbol);
    return (float*)p;
}

extern "C" void kernel_launch(void* const* d_in, const int* in_sizes, int n_in,
                              void* d_out, int out_size)
{
    (void)in_sizes; (void)n_in; (void)out_size;
    const float* feat0     = (const float*)d_in[0];
    const float* feat1     = (const float*)d_in[1];
    const float* flow_init = (const float*)d_in[2];
    const float* lc_w1 = (const float*)d_in[3];
    const float* lc_b1 = (const float*)d_in[4];
    const float* lc_w2 = (const float*)d_in[5];
    const float* lc_b2 = (const float*)d_in[6];
    const float* qw    = (const float*)d_in[7];
    const float* qb    = (const float*)d_in[8];
    const float* kw    = (const float*)d_in[9];
    const float* kb    = (const float*)d_in[10];
    const float* fr_w1 = (const float*)d_in[11];
    const float* fr_b1 = (const float*)d_in[12];
    const float* fr_w2 = (const float*)d_in[13];
    const float* fr_b2 = (const float*)d_in[14];
    const float* fr_w3 = (const float*)d_in[15];
    const float* fr_b3 = (const float*)d_in[16];
    const float* cf_w1 = (const float*)d_in[17];
    const float* cf_b1 = (const float*)d_in[18];
    const float* cf_w2 = (const float*)d_in[19];
    const float* cf_b2 = (const float*)d_in[20];
    const float* cf_w3 = (const float*)d_in[21];
    const float* cf_b3 = (const float*)d_in[22];

    float* lf0   = sym_addr(g_lf0);
    float* lf1   = sym_addr(g_lf1);
    float* tmp   = sym_addr(g_tmp);
    float* xbuf  = sym_addr(g_x);
    float* ybuf  = sym_addr(g_y);
    float* flow  = sym_addr(g_flow);
    float* fi    = sym_addr(g_fi);
    float* hcat  = sym_addr(g_hcat);
    float* h2    = sym_addr(g_h2);
    float* Mbuf  = sym_addr(g_M);
    float* ubuf  = sym_addr(g_u);
    float* bvbuf = sym_addr(g_bv);
    float* cbuf  = sym_addr(g_c);
    float* bscal = sym_addr(g_bscal);
    float* out_flow = (float*)d_out;                 // [B,2,H,W]
    float* out_conf = (float*)d_out + BATCH * 2 * NPIX;  // [B,1,H,W]

    cudaFuncSetAttribute(fr_fused_kernel,
                         cudaFuncAttributeMaxDynamicSharedMemorySize, FR_SMEM_BYTES);

    // one-time prep of the fused attention matrices
    prepM_kernel<<<128, 128>>>(qw, kw, Mbuf);
    prepUV_kernel<<<1, 128>>>(qw, kw, qb, kb, ubuf, bvbuf, cbuf);

    const dim3 cblk(256);
    // local_conv on both features (hoisted out of the loop)
    conv3x3_db_kernel<16><<<dim3(4,4,BATCH*8), cblk>>>(feat0, lc_w1, lc_b1, tmp, 128, 128, ACT_GELU);
    conv3x3_db_kernel<16><<<dim3(4,4,BATCH*8), cblk>>>(tmp,   lc_w2, lc_b2, lf0, 128, 128, ACT_NONE);
    conv3x3_db_kernel<16><<<dim3(4,4,BATCH*8), cblk>>>(feat1, lc_w1, lc_b1, tmp, 128, 128, ACT_GELU);
    conv3x3_db_kernel<16><<<dim3(4,4,BATCH*8), cblk>>>(tmp,   lc_w2, lc_b2, lf1, 128, 128, ACT_NONE);

    copy_kernel<<<(BATCH*2*NPIX + 255)/256, 256>>>(flow, flow_init, BATCH*2*NPIX);

    for (int it = 0; it < ITERS; ++it) {
        warp_diff_kernel<<<dim3(2*HW, BATCH), 128>>>(lf0, lf1, flow, xbuf);
        gemm_y_kernel<<<BATCH*NPIX/128, 256>>>(xbuf, Mbuf, bvbuf, ybuf, bscal);
        attn_kernel<<<BATCH*NPIX/8, 256>>>(xbuf, ybuf, bscal, ubuf, cbuf, flow, fi);
        fr_fused_kernel<<<dim3(8,8,BATCH), 256, FR_SMEM_BYTES>>>(
            fi, fr_w1, fr_b1, fr_w2, fr_b2, fr_w3, fr_b3, flow);
    }

    // confidence head
    pack_kernel<<<dim3(HW, BATCH), 128>>>(feat0, feat1, flow, hcat);
    conv3x3_db_kernel<16><<<dim3(4,4,BATCH*8), cblk>>>(hcat, cf_w1, cf_b1, tmp, 258, 128, ACT_GELU);
    conv3x3_db_kernel<16><<<dim3(4,4,BATCH*4), cblk>>>(tmp,  cf_w2, cf_b2, h2,  128, 64,  ACT_GELU);
    conv3x3_kernel<2><<<dim3(4,4,BATCH),  cblk>>>(h2, cf_w3, cf_b3, out_conf, 64, 1, ACT_SIGM);

    copy_kernel<<<(BATCH*2*NPIX + 255)/256, 256>>>(out_flow, flow, BATCH*2*NPIX);
}

// round 7
// speedup vs baseline: 1.5645x; 1.0062x over previous
#include <cuda_runtime.h>
#include <stdint.h>
#include <math.h>

#define HW     128
#define BATCH  2
#define CH     128
#define NPIX   (HW*HW)            // 16384
#define ITERS  10

// ---------------- scratch (static device allocations; no cudaMalloc) ----------------
__device__ float g_lf0 [BATCH*CH*NPIX];
__device__ float g_lf1 [BATCH*CH*NPIX];
__device__ float g_tmp [BATCH*CH*NPIX];
__device__ float g_tmp2[BATCH*CH*NPIX];
__device__ float g_x   [BATCH*NPIX*CH];      // channel-last attention input
__device__ float g_y   [BATCH*NPIX*CH];      // y = M x (channel-last)
__device__ float g_flow[BATCH*2*NPIX];
__device__ float g_fi  [BATCH*2*NPIX];
__device__ float g_hcat[BATCH*258*NPIX];
__device__ float g_h2  [BATCH*64*NPIX];
__device__ float g_M   [CH*CH];              // Wq^T Wk
__device__ float g_u   [CH];                 // Wq^T kb
__device__ float g_bv  [CH];                 // Wk^T qb
__device__ float g_c   [1];                  // qb . kb
__device__ float g_bscal[BATCH*NPIX];        // bv . x per pixel

// ---------------- helpers ----------------
__device__ __forceinline__ float gelu_f(float v) {
    return 0.5f * v * (1.0f + erff(v * 0.70710678118654752f));
}
__device__ __forceinline__ float sigmoid_f(float v) {
    return 1.0f / (1.0f + expf(-v));
}

#define ACT_NONE 0
#define ACT_GELU 1
#define ACT_SIGM 2

// ---------------- prep: M = Wq^T Wk ; u = Wq^T kb ; bv = Wk^T qb ; c = qb.kb ----------------
__global__ void prepM_kernel(const float* __restrict__ qw, const float* __restrict__ kw,
                             float* __restrict__ M)
{
    int i = blockIdx.x, j = threadIdx.x;
    float s = 0.f;
    for (int d = 0; d < CH; d++)
        s += qw[d * CH + i] * kw[d * CH + j];
    M[i * CH + j] = s;
}

__global__ void prepUV_kernel(const float* __restrict__ qw, const float* __restrict__ kw,
                              const float* __restrict__ qb, const float* __restrict__ kb,
                              float* __restrict__ u, float* __restrict__ bv, float* __restrict__ c)
{
    int j = threadIdx.x;
    float su = 0.f, sb = 0.f;
    for (int d = 0; d < CH; d++) {
        su += qw[d * CH + j] * kb[d];
        sb += kw[d * CH + j] * qb[d];
    }
    u[j] = su;
    bv[j] = sb;
    if (j == 0) {
        float cc = 0.f;
        for (int d = 0; d < CH; d++) cc += qb[d] * kb[d];
        c[0] = cc;
    }
}

// ---------------- NCHW 3x3 conv (R3 single-buffered; dual input/output for merged launches) ----
// z covers nfeat*BATCH*nco: features select (in0,out0) vs (in1,out1).
template<int COT>
__global__ __launch_bounds__(256, 2) void conv3x3_kernel(
    const float* __restrict__ in0, const float* __restrict__ in1,
    const float* __restrict__ wgt, const float* __restrict__ bias,
    float* __restrict__ out0, float* __restrict__ out1,
    int Cin, int Cout, int act)
{
    __shared__ float s_in[8][34][34];
    __shared__ float s_w[8][COT][9];

    const int tid = threadIdx.x;
    const int tx = tid & 15, ty = tid >> 4;
    const int x0 = blockIdx.x * 32, y0 = blockIdx.y * 32;
    const int nco = (Cout + COT - 1) / COT;
    int bb  = blockIdx.z / nco;
    const int co0 = (blockIdx.z % nco) * COT;

    const float* in = in0;
    float* out = out0;
    if (bb >= BATCH) { in = in1; out = out1; bb -= BATCH; }

    float acc[COT][2][2];
    #pragma unroll
    for (int c = 0; c < COT; c++)
        #pragma unroll
        for (int i = 0; i < 2; i++)
            #pragma unroll
            for (int j = 0; j < 2; j++) acc[c][i][j] = 0.f;

    for (int c0 = 0; c0 < Cin; c0 += 8) {
        for (int idx = tid; idx < 8 * 1156; idx += 256) {
            int ci = idx / 1156;
            int r  = (idx % 1156) / 34;
            int cc = idx % 34;
            int gy = y0 - 1 + r, gx = x0 - 1 + cc;
            int cin = c0 + ci;
            float v = 0.f;
            if (cin < Cin && (unsigned)gy < (unsigned)HW && (unsigned)gx < (unsigned)HW)
                v = in[((size_t)(bb * Cin + cin) * HW + gy) * HW + gx];
            s_in[ci][r][cc] = v;
        }
        for (int idx = tid; idx < 8 * COT * 9; idx += 256) {
            int ci = idx / (COT * 9);
            int co = (idx % (COT * 9)) / 9;
            int k  = idx % 9;
            int cin = c0 + ci, cog = co0 + co;
            float v = 0.f;
            if (cin < Cin && cog < Cout)
                v = wgt[((size_t)cog * Cin + cin) * 9 + k];
            s_w[ci][co][k] = v;
        }
        __syncthreads();

        #pragma unroll
        for (int ci = 0; ci < 8; ci++) {
            float v[4][4];
            #pragma unroll
            for (int i = 0; i < 4; i++)
                #pragma unroll
                for (int j = 0; j < 4; j++)
                    v[i][j] = s_in[ci][ty * 2 + i][tx * 2 + j];
            #pragma unroll
            for (int co = 0; co < COT; co++) {
                float w0 = s_w[ci][co][0], w1 = s_w[ci][co][1], w2 = s_w[ci][co][2];
                float w3 = s_w[ci][co][3], w4 = s_w[ci][co][4], w5 = s_w[ci][co][5];
                float w6 = s_w[ci][co][6], w7 = s_w[ci][co][7], w8 = s_w[ci][co][8];
                #pragma unroll
                for (int i2 = 0; i2 < 2; i2++)
                    #pragma unroll
                    for (int j2 = 0; j2 < 2; j2++) {
                        float a = acc[co][i2][j2];
                        a += v[i2+0][j2+0] * w0;
                        a += v[i2+0][j2+1] * w1;
                        a += v[i2+0][j2+2] * w2;
                        a += v[i2+1][j2+0] * w3;
                        a += v[i2+1][j2+1] * w4;
                        a += v[i2+1][j2+2] * w5;
                        a += v[i2+2][j2+0] * w6;
                        a += v[i2+2][j2+1] * w7;
                        a += v[i2+2][j2+2] * w8;
                        acc[co][i2][j2] = a;
                    }
            }
        }
        __syncthreads();
    }

    #pragma unroll
    for (int co = 0; co < COT; co++) {
        int cog = co0 + co;
        if (cog >= Cout) break;
        float bv = bias[cog];
        #pragma unroll
        for (int i2 = 0; i2 < 2; i2++)
            #pragma unroll
            for (int j2 = 0; j2 < 2; j2++) {
                int oy = y0 + ty * 2 + i2, ox = x0 + tx * 2 + j2;
                float v = acc[co][i2][j2] + bv;
                if (act == ACT_GELU) v = gelu_f(v);
                else if (act == ACT_SIGM) v = sigmoid_f(v);
                out[((size_t)(bb * Cout + cog) * HW + oy) * HW + ox] = v;
            }
    }
}

// ---------------- fused flow-refiner chain ----------------
#define FR_OFF_W1 0
#define FR_OFF_B1 288
#define FR_OFF_W2 304
#define FR_OFF_B2 2608
#define FR_OFF_W3 2624
#define FR_OFF_B3 2912
#define FR_OFF_FI 2916
#define FR_OFF_T1 3884
#define FR_OFF_T2 10284
#define FR_SMEM_FLOATS 15468
#define FR_SMEM_BYTES (FR_SMEM_FLOATS * 4)

__global__ __launch_bounds__(256) void fr_fused_kernel(
    const float* __restrict__ fi,
    const float* __restrict__ w1, const float* __restrict__ b1,
    const float* __restrict__ w2, const float* __restrict__ b2,
    const float* __restrict__ w3, const float* __restrict__ b3,
    float* __restrict__ flow)
{
    extern __shared__ float sm[];
    const int tid = threadIdx.x;
    const int x0 = blockIdx.x * 16, y0 = blockIdx.y * 16;
    const int b = blockIdx.z;

    for (int u = tid; u < 288;  u += 256) sm[FR_OFF_W1 + u] = w1[u];
    for (int u = tid; u < 16;   u += 256) sm[FR_OFF_B1 + u] = b1[u];
    for (int u = tid; u < 2304; u += 256) sm[FR_OFF_W2 + u] = w2[u];
    for (int u = tid; u < 16;   u += 256) sm[FR_OFF_B2 + u] = b2[u];
    for (int u = tid; u < 288;  u += 256) sm[FR_OFF_W3 + u] = w3[u];
    for (int u = tid; u < 2;    u += 256) sm[FR_OFF_B3 + u] = b3[u];
    for (int u = tid; u < 2 * 484; u += 256) {
        int ci = u / 484;
        int rem = u % 484;
        int r = rem / 22, c = rem % 22;
        int gy = y0 - 3 + r, gx = x0 - 3 + c;
        float v = 0.f;
        if ((unsigned)gy < (unsigned)HW && (unsigned)gx < (unsigned)HW)
            v = fi[(size_t)(b * 2 + ci) * NPIX + gy * HW + gx];
        sm[FR_OFF_FI + u] = v;
    }
    __syncthreads();

    for (int u = tid; u < 16 * 400; u += 256) {
        int co = u / 400;
        int rem = u % 400;
        int r = rem / 20, c = rem % 20;
        int gy = y0 - 2 + r, gx = x0 - 2 + c;
        float v = 0.f;
        if ((unsigned)gy < (unsigned)HW && (unsigned)gx < (unsigned)HW) {
            float s = sm[FR_OFF_B1 + co];
            #pragma unroll
            for (int ci = 0; ci < 2; ci++)
                #pragma unroll
                for (int dy = 0; dy < 3; dy++)
                    #pragma unroll
                    for (int dx = 0; dx < 3; dx++)
                        s += sm[FR_OFF_FI + (ci * 22 + r + dy) * 22 + c + dx]
                           * sm[FR_OFF_W1 + (co * 2 + ci) * 9 + dy * 3 + dx];
            v = gelu_f(s);
        }
        sm[FR_OFF_T1 + u] = v;
    }
    __syncthreads();

    for (int u = tid; u < 16 * 324; u += 256) {
        int co = u / 324;
        int rem = u % 324;
        int r = rem / 18, c = rem % 18;
        int gy = y0 - 1 + r, gx = x0 - 1 + c;
        float v = 0.f;
        if ((unsigned)gy < (unsigned)HW && (unsigned)gx < (unsigned)HW) {
            float s = sm[FR_OFF_B2 + co];
            #pragma unroll
            for (int ci = 0; ci < 16; ci++) {
                const float* t1p = &sm[FR_OFF_T1 + (ci * 20 + r) * 20 + c];
                const float* wp  = &sm[FR_OFF_W2 + (co * 16 + ci) * 9];
                s += t1p[0]  * wp[0] + t1p[1]  * wp[1] + t1p[2]  * wp[2];
                s += t1p[20] * wp[3] + t1p[21] * wp[4] + t1p[22] * wp[5];
                s += t1p[40] * wp[6] + t1p[41] * wp[7] + t1p[42] * wp[8];
            }
            v = gelu_f(s);
        }
        sm[FR_OFF_T2 + u] = v;
    }
    __syncthreads();

    for (int u = tid; u < 2 * 256; u += 256) {
        int f = u / 256;
        int rem = u % 256;
        int r = rem / 16, c = rem % 16;
        float s = sm[FR_OFF_B3 + f];
        #pragma unroll
        for (int ci = 0; ci < 16; ci++) {
            const float* t2p = &sm[FR_OFF_T2 + (ci * 18 + r) * 18 + c];
            const float* wp  = &sm[FR_OFF_W3 + (f * 16 + ci) * 9];
            s += t2p[0]  * wp[0] + t2p[1]  * wp[1] + t2p[2]  * wp[2];
            s += t2p[18] * wp[3] + t2p[19] * wp[4] + t2p[20] * wp[5];
            s += t2p[36] * wp[6] + t2p[37] * wp[7] + t2p[38] * wp[8];
        }
        int gy = y0 + r, gx = x0 + c;
        flow[(size_t)(b * 2 + f) * NPIX + gy * HW + gx] += s;
    }
}

// ---------------- warp + diff + L2-normalize; x = 1 - diffn channel-last ----------------
__global__ __launch_bounds__(128) void warp_diff_kernel(
    const float* __restrict__ lf0, const float* __restrict__ lf1,
    const float* __restrict__ flow, float* __restrict__ xout)
{
    __shared__ float s_diff[64][129];
    __shared__ float s_ssq[128];
    __shared__ float s_rinv[64];

    const int tid = threadIdx.x;
    const int b = blockIdx.y;
    const int y = blockIdx.x >> 1;
    const int xbase = (blockIdx.x & 1) * 64;
    const int px = tid & 63;
    const int half = tid >> 6;
    const int x = xbase + px;

    float fx = flow[(b * 2 + 0) * NPIX + y * HW + x];
    float fy = flow[(b * 2 + 1) * NPIX + y * HW + x];
    float xs = fminf(fmaxf((float)x + fx, 0.f), 127.f);
    float ys = fminf(fmaxf((float)y + fy, 0.f), 127.f);
    float x0f = floorf(xs), y0f = floorf(ys);
    int ix0 = (int)x0f, iy0 = (int)y0f;
    int ix1 = min(ix0 + 1, 127), iy1 = min(iy0 + 1, 127);
    float wx = xs - x0f, wy = ys - y0f;
    float w00 = (1.f - wx) * (1.f - wy), w01 = wx * (1.f - wy);
    float w10 = (1.f - wx) * wy,         w11 = wx * wy;
    int o00 = iy0 * HW + ix0, o01 = iy0 * HW + ix1;
    int o10 = iy1 * HW + ix0, o11 = iy1 * HW + ix1;

    const float* lf1b = lf1 + (size_t)b * CH * NPIX;
    const float* lf0b = lf0 + (size_t)b * CH * NPIX;
    const int here = y * HW + x;

    float ssq = 0.f;
    for (int c = half * 64; c < half * 64 + 64; ++c) {
        const float* p = lf1b + (size_t)c * NPIX;
        float wv = w00 * p[o00] + w01 * p[o01] + w10 * p[o10] + w11 * p[o11];
        float d = lf0b[(size_t)c * NPIX + here] - wv;
        s_diff[px][c] = d;
        ssq += d * d;
    }
    s_ssq[tid] = ssq;
    __syncthreads();
    if (tid < 64) {
        float s = s_ssq[tid] + s_ssq[tid + 64];
        s_rinv[tid] = 1.f / fmaxf(sqrtf(s), 1e-12f);
    }
    __syncthreads();

    float* xb = xout + ((size_t)b * NPIX + y * HW + xbase) * CH;
    for (int p2 = 0; p2 < 64; ++p2)
        xb[(size_t)p2 * CH + tid] = 1.f - s_diff[p2][tid] * s_rinv[p2];
}

// ---------------- y = M x : [32768,128] x M[128,128] + bscal = bv.x ----------------
__global__ __launch_bounds__(256) void gemm_y_kernel(
    const float* __restrict__ X, const float* __restrict__ M,
    const float* __restrict__ bv,
    float* __restrict__ Y, float* __restrict__ bscal)
{
    __shared__ float As[8][132];
    __shared__ float Bs[8][132];
    __shared__ float sbv[128];

    const int tid = threadIdx.x;
    const int tx = tid & 15, ty = tid >> 4;
    const int m0 = blockIdx.x * 128;

    if (tid < 128) sbv[tid] = bv[tid];
    __syncthreads();

    float acc[8][8];
    #pragma unroll
    for (int i = 0; i < 8; i++)
        #pragma unroll
        for (int j = 0; j < 8; j++) acc[i][j] = 0.f;

    const int row  = tid >> 1;
    const int part = tid & 1;
    float bdot = 0.f;

    for (int kk = 0; kk < 128; kk += 8) {
        float4 a = *(const float4*)&X[(size_t)(m0 + row) * 128 + kk + part * 4];
        float4 b = *(const float4*)&M[(size_t)row * 128 + kk + part * 4];
        int kb4 = kk + part * 4;
        bdot += a.x * sbv[kb4+0] + a.y * sbv[kb4+1] + a.z * sbv[kb4+2] + a.w * sbv[kb4+3];
        As[part*4+0][row] = a.x; As[part*4+1][row] = a.y;
        As[part*4+2][row] = a.z; As[part*4+3][row] = a.w;
        Bs[part*4+0][row] = b.x; Bs[part*4+1][row] = b.y;
        Bs[part*4+2][row] = b.z; Bs[part*4+3][row] = b.w;
        __syncthreads();
        #pragma unroll
        for (int k = 0; k < 8; k++) {
            float af[8], bf[8];
            *(float4*)&af[0] = *(const float4*)&As[k][ty * 8];
            *(float4*)&af[4] = *(const float4*)&As[k][ty * 8 + 4];
            *(float4*)&bf[0] = *(const float4*)&Bs[k][tx * 8];
            *(float4*)&bf[4] = *(const float4*)&Bs[k][tx * 8 + 4];
            #pragma unroll
            for (int i = 0; i < 8; i++)
                #pragma unroll
                for (int j = 0; j < 8; j++)
                    acc[i][j] += af[i] * bf[j];
        }
        __syncthreads();
    }

    float other = __shfl_xor_sync(0xffffffffu, bdot, 1);
    if (part == 0) bscal[m0 + row] = bdot + other;

    #pragma unroll
    for (int i = 0; i < 8; i++) {
        int m = m0 + ty * 8 + i;
        #pragma unroll
        for (int j = 0; j < 8; j++)
            Y[(size_t)m * 128 + tx * 8 + j] = acc[i][j] + 0.f;
    }
}

// ---------------- smem-tiled 25-tap local attention ----------------
// block: 32x2 px tile, 256 threads = 64 px x 4 subs (32 ch each).
// lane mapping: sub = (lane>>3)&3 so each LDS.128 quarter-warp phase has a
// fixed sub and 8 consecutive columns -> conflict-free smem reads.
#define AT_SY_PX 132                     // per-pixel channel stride in smem
#define AT_OFF_SX (6*36*AT_SY_PX)        // 28512
#define AT_OFF_SB (AT_OFF_SX + 2*32*AT_SY_PX)  // +8448 = 36960
#define AT_OFF_SF (AT_OFF_SB + 216)            // 37176
#define AT_SMEM_FLOATS (AT_OFF_SF + 432)       // 37608
#define AT_SMEM_BYTES (AT_SMEM_FLOATS * 4)     // 150432

__global__ __launch_bounds__(256) void attn_tiled_kernel(
    const float* __restrict__ X, const float* __restrict__ Y,
    const float* __restrict__ bscal, const float* __restrict__ uvec,
    const float* __restrict__ cconst,
    const float* __restrict__ flow, float* __restrict__ fi)
{
    extern __shared__ float sm[];
    const float SCALE = 0.08838834764831845f;   // 1/sqrt(128)
    const int tid = threadIdx.x;
    const int x0 = blockIdx.x * 32;
    const int y0 = blockIdx.y * 2;
    const int b  = blockIdx.z;
    const int base = b << 14;

    // stage Y halo tile [6][36][128] (zero OOB)
    for (int i = tid; i < 6 * 36 * 32; i += 256) {
        int pos = i >> 5, c4 = (i & 31) * 4;
        int r = pos / 36, cc = pos % 36;
        int gy = y0 - 2 + r, gx = x0 - 2 + cc;
        float4 v = make_float4(0.f, 0.f, 0.f, 0.f);
        if ((unsigned)gy < (unsigned)HW && (unsigned)gx < (unsigned)HW)
            v = *(const float4*)&Y[((size_t)(base + gy * HW + gx)) * 128 + c4];
        *(float4*)&sm[(r * 36 + cc) * AT_SY_PX + c4] = v;
    }
    // stage X tile [2][32][128]
    for (int i = tid; i < 2 * 32 * 32; i += 256) {
        int pos = i >> 5, c4 = (i & 31) * 4;
        int py = pos >> 5, px = pos & 31;
        float4 v = *(const float4*)&X[((size_t)(base + (y0 + py) * HW + x0 + px)) * 128 + c4];
        *(float4*)&sm[AT_OFF_SX + (py * 32 + px) * AT_SY_PX + c4] = v;
    }
    // stage bscal + flow halo tiles [6][36]
    for (int i = tid; i < 216; i += 256) {
        int r = i / 36, cc = i % 36;
        int gy = y0 - 2 + r, gx = x0 - 2 + cc;
        bool ok = ((unsigned)gy < (unsigned)HW) && ((unsigned)gx < (unsigned)HW);
        int n = base + gy * HW + gx;
        sm[AT_OFF_SB + i]       = ok ? bscal[n] : 0.f;
        sm[AT_OFF_SF + i]       = ok ? flow[(size_t)(b * 2 + 0) * NPIX + gy * HW + gx] : 0.f;
        sm[AT_OFF_SF + 216 + i] = ok ? flow[(size_t)(b * 2 + 1) * NPIX + gy * HW + gx] : 0.f;
    }
    __syncthreads();

    const int lane = tid & 31;
    const int warp = tid >> 5;
    const int sub  = lane >> 3;                // 0..3  (channel chunk)
    const int pxl  = warp * 8 + (lane & 7);    // 0..63 pixel within tile
    const int ly = pxl >> 5, lx = pxl & 31;
    const int gy = y0 + ly, gx = x0 + lx;

    // x chunk in registers (32 ch)
    float4 xr[8];
    {
        const float* xp = &sm[AT_OFF_SX + (ly * 32 + lx) * AT_SY_PX + sub * 32];
        #pragma unroll
        for (int i = 0; i < 8; i++) xr[i] = *(const float4*)&xp[i * 4];
    }

    // ap = u . x_p
    float ap = 0.f;
    #pragma unroll
    for (int i = 0; i < 8; i++) {
        const float4 u4 = *(const float4*)&uvec[sub * 32 + i * 4];
        ap += xr[i].x * u4.x + xr[i].y * u4.y + xr[i].z * u4.z + xr[i].w * u4.w;
    }
    ap += __shfl_xor_sync(0xffffffffu, ap, 8);
    ap += __shfl_xor_sync(0xffffffffu, ap, 16);
    const float oobs = -(ap + cconst[0]) * SCALE;

    float s[25];
    #pragma unroll
    for (int t = 0; t < 25; t++) {
        const int dy = t / 5 - 2, dx = t % 5 - 2;
        const int ny = gy + dy, nx = gx + dx;
        if ((unsigned)ny < (unsigned)HW && (unsigned)nx < (unsigned)HW) {
            const int r = ly + dy + 2, cc = lx + dx + 2;
            const float* yp = &sm[(r * 36 + cc) * AT_SY_PX + sub * 32];
            float d = 0.f;
            #pragma unroll
            for (int i = 0; i < 8; i++) {
                float4 yv = *(const float4*)&yp[i * 4];
                d += xr[i].x * yv.x + xr[i].y * yv.y + xr[i].z * yv.z + xr[i].w * yv.w;
            }
            d += __shfl_xor_sync(0xffffffffu, d, 8);
            d += __shfl_xor_sync(0xffffffffu, d, 16);
            s[t] = (d + sm[AT_OFF_SB + r * 36 + cc]) * SCALE;
        } else {
            s[t] = oobs;
        }
    }

    float mx = s[0];
    #pragma unroll
    for (int t = 1; t < 25; t++) mx = fmaxf(mx, s[t]);
    float sum = 0.f;
    #pragma unroll
    for (int t = 0; t < 25; t++) { s[t] = expf(s[t] - mx); sum += s[t]; }

    if (sub == 0) {
        float inv = 1.f / sum;
        float c0 = 0.f, c1 = 0.f;
        #pragma unroll
        for (int t = 0; t < 25; t++) {
            const int dy = t / 5 - 2, dx = t % 5 - 2;
            const int ny = gy + dy, nx = gx + dx;
            if ((unsigned)ny < (unsigned)HW && (unsigned)nx < (unsigned)HW) {
                const int r = ly + dy + 2, cc = lx + dx + 2;
                float w = s[t] * inv;
                c0 += w * sm[AT_OFF_SF + r * 36 + cc];
                c1 += w * sm[AT_OFF_SF + 216 + r * 36 + cc];
            }
        }
        fi[(size_t)(b * 2 + 0) * NPIX + gy * HW + gx] = c0;
        fi[(size_t)(b * 2 + 1) * NPIX + gy * HW + gx] = c1;
    }
}

// ---------------- small utility kernels ----------------
__global__ void copy_kernel(float* __restrict__ dst, const float* __restrict__ src, int n) {
    int i = blockIdx.x * 256 + threadIdx.x;
    if (i < n) dst[i] = src[i];
}

// pack hcat = [feat0 | warp(feat1, flow) | flow] NCHW
__global__ __launch_bounds__(128) void pack_kernel(
    const float* __restrict__ feat0, const float* __restrict__ feat1,
    const float* __restrict__ flow, float* __restrict__ hcat)
{
    const int x = threadIdx.x;
    const int y = blockIdx.x;
    const int b = blockIdx.y;
    const int here = y * HW + x;

    float fx = flow[(b * 2 + 0) * NPIX + here];
    float fy = flow[(b * 2 + 1) * NPIX + here];
    float xs = fminf(fmaxf((float)x + fx, 0.f), 127.f);
    float ys = fminf(fmaxf((float)y + fy, 0.f), 127.f);
    float x0f = floorf(xs), y0f = floorf(ys);
    int ix0 = (int)x0f, iy0 = (int)y0f;
    int ix1 = min(ix0 + 1, 127), iy1 = min(iy0 + 1, 127);
    float wx = xs - x0f, wy = ys - y0f;
    float w00 = (1.f - wx) * (1.f - wy), w01 = wx * (1.f - wy);
    float w10 = (1.f - wx) * wy,         w11 = wx * wy;
    int o00 = iy0 * HW + ix0, o01 = iy0 * HW + ix1;
    int o10 = iy1 * HW + ix0, o11 = iy1 * HW + ix1;

    float* hb = hcat + (size_t)b * 258 * NPIX;
    const float* f0 = feat0 + (size_t)b * CH * NPIX;
    const float* f1 = feat1 + (size_t)b * CH * NPIX;

    for (int c = 0; c < CH; c++) {
        hb[(size_t)c * NPIX + here] = f0[(size_t)c * NPIX + here];
        const float* p = f1 + (size_t)c * NPIX;
        hb[(size_t)(CH + c) * NPIX + here] =
            w00 * p[o00] + w01 * p[o01] + w10 * p[o10] + w11 * p[o11];
    }
    hb[(size_t)256 * NPIX + here] = fx;
    hb[(size_t)257 * NPIX + here] = fy;
}

// ---------------- host orchestration ----------------
static float* sym_addr(const void* symbol) {
    void* p = nullptr;
    cudaGetSymbolAddress(&p, symbol);
    return (float*)p;
}

extern "C" void kernel_launch(void* const* d_in, const int* in_sizes, int n_in,
                              void* d_out, int out_size)
{
    (void)in_sizes; (void)n_in; (void)out_size;
    const float* feat0     = (const float*)d_in[0];
    const float* feat1     = (const float*)d_in[1];
    const float* flow_init = (const float*)d_in[2];
    const float* lc_w1 = (const float*)d_in[3];
    const float* lc_b1 = (const float*)d_in[4];
    const float* lc_w2 = (const float*)d_in[5];
    const float* lc_b2 = (const float*)d_in[6];
    const float* qw    = (const float*)d_in[7];
    const float* qb    = (const float*)d_in[8];
    const float* kw    = (const float*)d_in[9];
    const float* kb    = (const float*)d_in[10];
    const float* fr_w1 = (const float*)d_in[11];
    const float* fr_b1 = (const float*)d_in[12];
    const float* fr_w2 = (const float*)d_in[13];
    const float* fr_b2 = (const float*)d_in[14];
    const float* fr_w3 = (const float*)d_in[15];
    const float* fr_b3 = (const float*)d_in[16];
    const float* cf_w1 = (const float*)d_in[17];
    const float* cf_b1 = (const float*)d_in[18];
    const float* cf_w2 = (const float*)d_in[19];
    const float* cf_b2 = (const float*)d_in[20];
    const float* cf_w3 = (const float*)d_in[21];
    const float* cf_b3 = (const float*)d_in[22];

    float* lf0   = sym_addr(g_lf0);
    float* lf1   = sym_addr(g_lf1);
    float* tmp   = sym_addr(g_tmp);
    float* tmp2  = sym_addr(g_tmp2);
    float* xbuf  = sym_addr(g_x);
    float* ybuf  = sym_addr(g_y);
    float* flow  = sym_addr(g_flow);
    float* fi    = sym_addr(g_fi);
    float* hcat  = sym_addr(g_hcat);
    float* h2    = sym_addr(g_h2);
    float* Mbuf  = sym_addr(g_M);
    float* ubuf  = sym_addr(g_u);
    float* bvbuf = sym_addr(g_bv);
    float* cbuf  = sym_addr(g_c);
    float* bscal = sym_addr(g_bscal);
    float* out_flow = (float*)d_out;
    float* out_conf = (float*)d_out + BATCH * 2 * NPIX;

    cudaFuncSetAttribute(fr_fused_kernel,
                         cudaFuncAttributeMaxDynamicSharedMemorySize, FR_SMEM_BYTES);
    cudaFuncSetAttribute(attn_tiled_kernel,
                         cudaFuncAttributeMaxDynamicSharedMemorySize, AT_SMEM_BYTES);

    // one-time prep of the fused attention matrices
    prepM_kernel<<<128, 128>>>(qw, kw, Mbuf);
    prepUV_kernel<<<1, 128>>>(qw, kw, qb, kb, ubuf, bvbuf, cbuf);

    const dim3 cblk(256);
    // local_conv on both features, merged launches (z = 2 features x BATCH x nco)
    conv3x3_kernel<16><<<dim3(4,4,2*BATCH*8), cblk>>>(feat0, feat1, lc_w1, lc_b1, tmp, tmp2, 128, 128, ACT_GELU);
    conv3x3_kernel<16><<<dim3(4,4,2*BATCH*8), cblk>>>(tmp,   tmp2,  lc_w2, lc_b2, lf0, lf1,  128, 128, ACT_NONE);

    copy_kernel<<<(BATCH*2*NPIX + 255)/256, 256>>>(flow, flow_init, BATCH*2*NPIX);

    for (int it = 0; it < ITERS; ++it) {
        warp_diff_kernel<<<dim3(2*HW, BATCH), 128>>>(lf0, lf1, flow, xbuf);
        gemm_y_kernel<<<BATCH*NPIX/128, 256>>>(xbuf, Mbuf, bvbuf, ybuf, bscal);
        attn_tiled_kernel<<<dim3(4, 64, BATCH), 256, AT_SMEM_BYTES>>>(
            xbuf, ybuf, bscal, ubuf, cbuf, flow, fi);
        fr_fused_kernel<<<dim3(8,8,BATCH), 256, FR_SMEM_BYTES>>>(
            fi, fr_w1, fr_b1, fr_w2, fr_b2, fr_w3, fr_b3, flow);
    }

    // confidence head
    pack_kernel<<<dim3(HW, BATCH), 128>>>(feat0, feat1, flow, hcat);
    conv3x3_kernel<16><<<dim3(4,4,BATCH*8), cblk>>>(hcat, hcat, cf_w1, cf_b1, tmp, tmp, 258, 128, ACT_GELU);
    conv3x3_kernel<16><<<dim3(4,4,BATCH*4), cblk>>>(tmp,  tmp,  cf_w2, cf_b2, h2,  h2,  128, 64,  ACT_GELU);
    conv3x3_kernel<2><<<dim3(4,4,BATCH),  cblk>>>(h2, h2, cf_w3, cf_b3, out_conf, out_conf, 64, 1, ACT_SIGM);

    copy_kernel<<<(BATCH*2*NPIX + 255)/256, 256>>>(out_flow, flow, BATCH*2*NPIX);
}

// round 8
// speedup vs baseline: 1.5892x; 1.0157x over previous
#include <cuda_runtime.h>
#include <stdint.h>
#include <math.h>

#define HW     128
#define BATCH  2
#define CH     128
#define NPIX   (HW*HW)            // 16384
#define ITERS  10

// ---------------- scratch (static device allocations; no cudaMalloc) ----------------
__device__ float g_lf0 [BATCH*CH*NPIX];
__device__ float g_lf1 [BATCH*CH*NPIX];
__device__ float g_tmp [BATCH*CH*NPIX];
__device__ float g_tmp2[BATCH*CH*NPIX];
__device__ float g_x   [BATCH*NPIX*CH];      // channel-last attention input
__device__ float g_y   [BATCH*NPIX*CH];      // y = M x (channel-last)
__device__ float g_flow[BATCH*2*NPIX];
__device__ float g_fi  [BATCH*2*NPIX];
__device__ float g_hcat[BATCH*258*NPIX];
__device__ float g_h2  [BATCH*64*NPIX];
__device__ float g_M   [CH*CH];              // Wq^T Wk
__device__ float g_u   [CH];                 // Wq^T kb
__device__ float g_bv  [CH];                 // Wk^T qb
__device__ float g_c   [1];                  // qb . kb
__device__ float g_bscal[BATCH*NPIX];        // bv . x per pixel

// ---------------- helpers ----------------
__device__ __forceinline__ float gelu_f(float v) {
    return 0.5f * v * (1.0f + erff(v * 0.70710678118654752f));
}
__device__ __forceinline__ float sigmoid_f(float v) {
    return 1.0f / (1.0f + expf(-v));
}

#define ACT_NONE 0
#define ACT_GELU 1
#define ACT_SIGM 2

// ---------------- prep: M = Wq^T Wk ; u = Wq^T kb ; bv = Wk^T qb ; c = qb.kb ----------------
__global__ void prepM_kernel(const float* __restrict__ qw, const float* __restrict__ kw,
                             float* __restrict__ M)
{
    int i = blockIdx.x, j = threadIdx.x;
    float s = 0.f;
    for (int d = 0; d < CH; d++)
        s += qw[d * CH + i] * kw[d * CH + j];
    M[i * CH + j] = s;
}

__global__ void prepUV_kernel(const float* __restrict__ qw, const float* __restrict__ kw,
                              const float* __restrict__ qb, const float* __restrict__ kb,
                              float* __restrict__ u, float* __restrict__ bv, float* __restrict__ c)
{
    int j = threadIdx.x;
    float su = 0.f, sb = 0.f;
    for (int d = 0; d < CH; d++) {
        su += qw[d * CH + j] * kb[d];
        sb += kw[d * CH + j] * qb[d];
    }
    u[j] = su;
    bv[j] = sb;
    if (j == 0) {
        float cc = 0.f;
        for (int d = 0; d < CH; d++) cc += qb[d] * kb[d];
        c[0] = cc;
    }
}

// ---------------- NCHW 3x3 conv (vectorized smem loads; dual in/out for merged launches) ----
// z covers nfeat*BATCH*nco; padded weight smem for LDS.128 broadcast.
template<int COT>
__global__ __launch_bounds__(256, 2) void conv3x3_kernel(
    const float* __restrict__ in0, const float* __restrict__ in1,
    const float* __restrict__ wgt, const float* __restrict__ bias,
    float* __restrict__ out0, float* __restrict__ out1,
    int Cin, int Cout, int act)
{
    __shared__ float s_in[8][34][34];
    __shared__ __align__(16) float s_w[8][COT][12];   // 9 used, padded to 12 for 16B alignment

    const int tid = threadIdx.x;
    const int tx = tid & 15, ty = tid >> 4;
    const int x0 = blockIdx.x * 32, y0 = blockIdx.y * 32;
    const int nco = (Cout + COT - 1) / COT;
    int bb  = blockIdx.z / nco;
    const int co0 = (blockIdx.z % nco) * COT;

    const float* in = in0;
    float* out = out0;
    if (bb >= BATCH) { in = in1; out = out1; bb -= BATCH; }

    float acc[COT][2][2];
    #pragma unroll
    for (int c = 0; c < COT; c++)
        #pragma unroll
        for (int i = 0; i < 2; i++)
            #pragma unroll
            for (int j = 0; j < 2; j++) acc[c][i][j] = 0.f;

    for (int c0 = 0; c0 < Cin; c0 += 8) {
        for (int idx = tid; idx < 8 * 1156; idx += 256) {
            int ci = idx / 1156;
            int r  = (idx % 1156) / 34;
            int cc = idx % 34;
            int gy = y0 - 1 + r, gx = x0 - 1 + cc;
            int cin = c0 + ci;
            float v = 0.f;
            if (cin < Cin && (unsigned)gy < (unsigned)HW && (unsigned)gx < (unsigned)HW)
                v = in[((size_t)(bb * Cin + cin) * HW + gy) * HW + gx];
            s_in[ci][r][cc] = v;
        }
        for (int idx = tid; idx < 8 * COT * 9; idx += 256) {
            int ci = idx / (COT * 9);
            int co = (idx % (COT * 9)) / 9;
            int k  = idx % 9;
            int cin = c0 + ci, cog = co0 + co;
            float v = 0.f;
            if (cin < Cin && cog < Cout)
                v = wgt[((size_t)cog * Cin + cin) * 9 + k];
            s_w[ci][co][k] = v;
        }
        __syncthreads();

        #pragma unroll
        for (int ci = 0; ci < 8; ci++) {
            // 4x4 pixel patch via float2 loads (even column base -> 8B aligned)
            float v[4][4];
            #pragma unroll
            for (int i = 0; i < 4; i++) {
                float2 a = *(const float2*)&s_in[ci][ty * 2 + i][tx * 2];
                float2 b = *(const float2*)&s_in[ci][ty * 2 + i][tx * 2 + 2];
                v[i][0] = a.x; v[i][1] = a.y; v[i][2] = b.x; v[i][3] = b.y;
            }
            #pragma unroll
            for (int co = 0; co < COT; co++) {
                // 9 weights via 2x LDS.128 + 1x LDS.32 (uniform -> broadcast)
                float4 wa = *(const float4*)&s_w[ci][co][0];
                float4 wb = *(const float4*)&s_w[ci][co][4];
                float w8  = s_w[ci][co][8];
                #pragma unroll
                for (int i2 = 0; i2 < 2; i2++)
                    #pragma unroll
                    for (int j2 = 0; j2 < 2; j2++) {
                        float a = acc[co][i2][j2];
                        a += v[i2+0][j2+0] * wa.x;
                        a += v[i2+0][j2+1] * wa.y;
                        a += v[i2+0][j2+2] * wa.z;
                        a += v[i2+1][j2+0] * wa.w;
                        a += v[i2+1][j2+1] * wb.x;
                        a += v[i2+1][j2+2] * wb.y;
                        a += v[i2+2][j2+0] * wb.z;
                        a += v[i2+2][j2+1] * wb.w;
                        a += v[i2+2][j2+2] * w8;
                        acc[co][i2][j2] = a;
                    }
            }
        }
        __syncthreads();
    }

    #pragma unroll
    for (int co = 0; co < COT; co++) {
        int cog = co0 + co;
        if (cog >= Cout) break;
        float bv = bias[cog];
        #pragma unroll
        for (int i2 = 0; i2 < 2; i2++)
            #pragma unroll
            for (int j2 = 0; j2 < 2; j2++) {
                int oy = y0 + ty * 2 + i2, ox = x0 + tx * 2 + j2;
                float v = acc[co][i2][j2] + bv;
                if (act == ACT_GELU) v = gelu_f(v);
                else if (act == ACT_SIGM) v = sigmoid_f(v);
                out[((size_t)(bb * Cout + cog) * HW + oy) * HW + ox] = v;
            }
    }
}

// ---------------- fused flow-refiner chain ----------------
#define FR_OFF_W1 0
#define FR_OFF_B1 288
#define FR_OFF_W2 304
#define FR_OFF_B2 2608
#define FR_OFF_W3 2624
#define FR_OFF_B3 2912
#define FR_OFF_FI 2916
#define FR_OFF_T1 3884
#define FR_OFF_T2 10284
#define FR_SMEM_FLOATS 15468
#define FR_SMEM_BYTES (FR_SMEM_FLOATS * 4)

__global__ __launch_bounds__(256) void fr_fused_kernel(
    const float* __restrict__ fi,
    const float* __restrict__ w1, const float* __restrict__ b1,
    const float* __restrict__ w2, const float* __restrict__ b2,
    const float* __restrict__ w3, const float* __restrict__ b3,
    float* __restrict__ flow)
{
    extern __shared__ float sm[];
    const int tid = threadIdx.x;
    const int x0 = blockIdx.x * 16, y0 = blockIdx.y * 16;
    const int b = blockIdx.z;

    for (int u = tid; u < 288;  u += 256) sm[FR_OFF_W1 + u] = w1[u];
    for (int u = tid; u < 16;   u += 256) sm[FR_OFF_B1 + u] = b1[u];
    for (int u = tid; u < 2304; u += 256) sm[FR_OFF_W2 + u] = w2[u];
    for (int u = tid; u < 16;   u += 256) sm[FR_OFF_B2 + u] = b2[u];
    for (int u = tid; u < 288;  u += 256) sm[FR_OFF_W3 + u] = w3[u];
    for (int u = tid; u < 2;    u += 256) sm[FR_OFF_B3 + u] = b3[u];
    for (int u = tid; u < 2 * 484; u += 256) {
        int ci = u / 484;
        int rem = u % 484;
        int r = rem / 22, c = rem % 22;
        int gy = y0 - 3 + r, gx = x0 - 3 + c;
        float v = 0.f;
        if ((unsigned)gy < (unsigned)HW && (unsigned)gx < (unsigned)HW)
            v = fi[(size_t)(b * 2 + ci) * NPIX + gy * HW + gx];
        sm[FR_OFF_FI + u] = v;
    }
    __syncthreads();

    for (int u = tid; u < 16 * 400; u += 256) {
        int co = u / 400;
        int rem = u % 400;
        int r = rem / 20, c = rem % 20;
        int gy = y0 - 2 + r, gx = x0 - 2 + c;
        float v = 0.f;
        if ((unsigned)gy < (unsigned)HW && (unsigned)gx < (unsigned)HW) {
            float s = sm[FR_OFF_B1 + co];
            #pragma unroll
            for (int ci = 0; ci < 2; ci++)
                #pragma unroll
                for (int dy = 0; dy < 3; dy++)
                    #pragma unroll
                    for (int dx = 0; dx < 3; dx++)
                        s += sm[FR_OFF_FI + (ci * 22 + r + dy) * 22 + c + dx]
                           * sm[FR_OFF_W1 + (co * 2 + ci) * 9 + dy * 3 + dx];
            v = gelu_f(s);
        }
        sm[FR_OFF_T1 + u] = v;
    }
    __syncthreads();

    for (int u = tid; u < 16 * 324; u += 256) {
        int co = u / 324;
        int rem = u % 324;
        int r = rem / 18, c = rem % 18;
        int gy = y0 - 1 + r, gx = x0 - 1 + c;
        float v = 0.f;
        if ((unsigned)gy < (unsigned)HW && (unsigned)gx < (unsigned)HW) {
            float s = sm[FR_OFF_B2 + co];
            #pragma unroll
            for (int ci = 0; ci < 16; ci++) {
                const float* t1p = &sm[FR_OFF_T1 + (ci * 20 + r) * 20 + c];
                const float* wp  = &sm[FR_OFF_W2 + (co * 16 + ci) * 9];
                s += t1p[0]  * wp[0] + t1p[1]  * wp[1] + t1p[2]  * wp[2];
                s += t1p[20] * wp[3] + t1p[21] * wp[4] + t1p[22] * wp[5];
                s += t1p[40] * wp[6] + t1p[41] * wp[7] + t1p[42] * wp[8];
            }
            v = gelu_f(s);
        }
        sm[FR_OFF_T2 + u] = v;
    }
    __syncthreads();

    for (int u = tid; u < 2 * 256; u += 256) {
        int f = u / 256;
        int rem = u % 256;
        int r = rem / 16, c = rem % 16;
        float s = sm[FR_OFF_B3 + f];
        #pragma unroll
        for (int ci = 0; ci < 16; ci++) {
            const float* t2p = &sm[FR_OFF_T2 + (ci * 18 + r) * 18 + c];
            const float* wp  = &sm[FR_OFF_W3 + (f * 16 + ci) * 9];
            s += t2p[0]  * wp[0] + t2p[1]  * wp[1] + t2p[2]  * wp[2];
            s += t2p[18] * wp[3] + t2p[19] * wp[4] + t2p[20] * wp[5];
            s += t2p[36] * wp[6] + t2p[37] * wp[7] + t2p[38] * wp[8];
        }
        int gy = y0 + r, gx = x0 + c;
        flow[(size_t)(b * 2 + f) * NPIX + gy * HW + gx] += s;
    }
}

// ---------------- warp + diff + L2-normalize; x = 1 - diffn channel-last ----------------
__global__ __launch_bounds__(128) void warp_diff_kernel(
    const float* __restrict__ lf0, const float* __restrict__ lf1,
    const float* __restrict__ flow, float* __restrict__ xout)
{
    __shared__ float s_diff[64][129];
    __shared__ float s_ssq[128];
    __shared__ float s_rinv[64];

    const int tid = threadIdx.x;
    const int b = blockIdx.y;
    const int y = blockIdx.x >> 1;
    const int xbase = (blockIdx.x & 1) * 64;
    const int px = tid & 63;
    const int half = tid >> 6;
    const int x = xbase + px;

    float fx = flow[(b * 2 + 0) * NPIX + y * HW + x];
    float fy = flow[(b * 2 + 1) * NPIX + y * HW + x];
    float xs = fminf(fmaxf((float)x + fx, 0.f), 127.f);
    float ys = fminf(fmaxf((float)y + fy, 0.f), 127.f);
    float x0f = floorf(xs), y0f = floorf(ys);
    int ix0 = (int)x0f, iy0 = (int)y0f;
    int ix1 = min(ix0 + 1, 127), iy1 = min(iy0 + 1, 127);
    float wx = xs - x0f, wy = ys - y0f;
    float w00 = (1.f - wx) * (1.f - wy), w01 = wx * (1.f - wy);
    float w10 = (1.f - wx) * wy,         w11 = wx * wy;
    int o00 = iy0 * HW + ix0, o01 = iy0 * HW + ix1;
    int o10 = iy1 * HW + ix0, o11 = iy1 * HW + ix1;

    const float* lf1b = lf1 + (size_t)b * CH * NPIX;
    const float* lf0b = lf0 + (size_t)b * CH * NPIX;
    const int here = y * HW + x;

    float ssq = 0.f;
    for (int c = half * 64; c < half * 64 + 64; ++c) {
        const float* p = lf1b + (size_t)c * NPIX;
        float wv = w00 * p[o00] + w01 * p[o01] + w10 * p[o10] + w11 * p[o11];
        float d = lf0b[(size_t)c * NPIX + here] - wv;
        s_diff[px][c] = d;
        ssq += d * d;
    }
    s_ssq[tid] = ssq;
    __syncthreads();
    if (tid < 64) {
        float s = s_ssq[tid] + s_ssq[tid + 64];
        s_rinv[tid] = 1.f / fmaxf(sqrtf(s), 1e-12f);
    }
    __syncthreads();

    float* xb = xout + ((size_t)b * NPIX + y * HW + xbase) * CH;
    for (int p2 = 0; p2 < 64; ++p2)
        xb[(size_t)p2 * CH + tid] = 1.f - s_diff[p2][tid] * s_rinv[p2];
}

// ---------------- y = M x : [32768,128] x M[128,128] + bscal = bv.x ----------------
__global__ __launch_bounds__(256) void gemm_y_kernel(
    const float* __restrict__ X, const float* __restrict__ M,
    const float* __restrict__ bv,
    float* __restrict__ Y, float* __restrict__ bscal)
{
    __shared__ float As[8][132];
    __shared__ float Bs[8][132];
    __shared__ float sbv[128];

    const int tid = threadIdx.x;
    const int tx = tid & 15, ty = tid >> 4;
    const int m0 = blockIdx.x * 128;

    if (tid < 128) sbv[tid] = bv[tid];
    __syncthreads();

    float acc[8][8];
    #pragma unroll
    for (int i = 0; i < 8; i++)
        #pragma unroll
        for (int j = 0; j < 8; j++) acc[i][j] = 0.f;

    const int row  = tid >> 1;
    const int part = tid & 1;
    float bdot = 0.f;

    for (int kk = 0; kk < 128; kk += 8) {
        float4 a = *(const float4*)&X[(size_t)(m0 + row) * 128 + kk + part * 4];
        float4 b = *(const float4*)&M[(size_t)row * 128 + kk + part * 4];
        int kb4 = kk + part * 4;
        bdot += a.x * sbv[kb4+0] + a.y * sbv[kb4+1] + a.z * sbv[kb4+2] + a.w * sbv[kb4+3];
        As[part*4+0][row] = a.x; As[part*4+1][row] = a.y;
        As[part*4+2][row] = a.z; As[part*4+3][row] = a.w;
        Bs[part*4+0][row] = b.x; Bs[part*4+1][row] = b.y;
        Bs[part*4+2][row] = b.z; Bs[part*4+3][row] = b.w;
        __syncthreads();
        #pragma unroll
        for (int k = 0; k < 8; k++) {
            float af[8], bf[8];
            *(float4*)&af[0] = *(const float4*)&As[k][ty * 8];
            *(float4*)&af[4] = *(const float4*)&As[k][ty * 8 + 4];
            *(float4*)&bf[0] = *(const float4*)&Bs[k][tx * 8];
            *(float4*)&bf[4] = *(const float4*)&Bs[k][tx * 8 + 4];
            #pragma unroll
            for (int i = 0; i < 8; i++)
                #pragma unroll
                for (int j = 0; j < 8; j++)
                    acc[i][j] += af[i] * bf[j];
        }
        __syncthreads();
    }

    float other = __shfl_xor_sync(0xffffffffu, bdot, 1);
    if (part == 0) bscal[m0 + row] = bdot + other;

    #pragma unroll
    for (int i = 0; i < 8; i++) {
        int m = m0 + ty * 8 + i;
        #pragma unroll
        for (int j = 0; j < 8; j++)
            Y[(size_t)m * 128 + tx * 8 + j] = acc[i][j];
    }
}

// ---------------- smem-tiled 25-tap local attention ----------------
#define AT_SY_PX 132
#define AT_OFF_SX (6*36*AT_SY_PX)
#define AT_OFF_SB (AT_OFF_SX + 2*32*AT_SY_PX)
#define AT_OFF_SF (AT_OFF_SB + 216)
#define AT_SMEM_FLOATS (AT_OFF_SF + 432)
#define AT_SMEM_BYTES (AT_SMEM_FLOATS * 4)

__global__ __launch_bounds__(256) void attn_tiled_kernel(
    const float* __restrict__ X, const float* __restrict__ Y,
    const float* __restrict__ bscal, const float* __restrict__ uvec,
    const float* __restrict__ cconst,
    const float* __restrict__ flow, float* __restrict__ fi)
{
    extern __shared__ float sm[];
    const float SCALE = 0.08838834764831845f;   // 1/sqrt(128)
    const int tid = threadIdx.x;
    const int x0 = blockIdx.x * 32;
    const int y0 = blockIdx.y * 2;
    const int b  = blockIdx.z;
    const int base = b << 14;

    for (int i = tid; i < 6 * 36 * 32; i += 256) {
        int pos = i >> 5, c4 = (i & 31) * 4;
        int r = pos / 36, cc = pos % 36;
        int gy = y0 - 2 + r, gx = x0 - 2 + cc;
        float4 v = make_float4(0.f, 0.f, 0.f, 0.f);
        if ((unsigned)gy < (unsigned)HW && (unsigned)gx < (unsigned)HW)
            v = *(const float4*)&Y[((size_t)(base + gy * HW + gx)) * 128 + c4];
        *(float4*)&sm[(r * 36 + cc) * AT_SY_PX + c4] = v;
    }
    for (int i = tid; i < 2 * 32 * 32; i += 256) {
        int pos = i >> 5, c4 = (i & 31) * 4;
        int py = pos >> 5, px = pos & 31;
        float4 v = *(const float4*)&X[((size_t)(base + (y0 + py) * HW + x0 + px)) * 128 + c4];
        *(float4*)&sm[AT_OFF_SX + (py * 32 + px) * AT_SY_PX + c4] = v;
    }
    for (int i = tid; i < 216; i += 256) {
        int r = i / 36, cc = i % 36;
        int gy = y0 - 2 + r, gx = x0 - 2 + cc;
        bool ok = ((unsigned)gy < (unsigned)HW) && ((unsigned)gx < (unsigned)HW);
        int n = base + gy * HW + gx;
        sm[AT_OFF_SB + i]       = ok ? bscal[n] : 0.f;
        sm[AT_OFF_SF + i]       = ok ? flow[(size_t)(b * 2 + 0) * NPIX + gy * HW + gx] : 0.f;
        sm[AT_OFF_SF + 216 + i] = ok ? flow[(size_t)(b * 2 + 1) * NPIX + gy * HW + gx] : 0.f;
    }
    __syncthreads();

    const int lane = tid & 31;
    const int warp = tid >> 5;
    const int sub  = lane >> 3;
    const int pxl  = warp * 8 + (lane & 7);
    const int ly = pxl >> 5, lx = pxl & 31;
    const int gy = y0 + ly, gx = x0 + lx;

    float4 xr[8];
    {
        const float* xp = &sm[AT_OFF_SX + (ly * 32 + lx) * AT_SY_PX + sub * 32];
        #pragma unroll
        for (int i = 0; i < 8; i++) xr[i] = *(const float4*)&xp[i * 4];
    }

    float ap = 0.f;
    #pragma unroll
    for (int i = 0; i < 8; i++) {
        const float4 u4 = *(const float4*)&uvec[sub * 32 + i * 4];
        ap += xr[i].x * u4.x + xr[i].y * u4.y + xr[i].z * u4.z + xr[i].w * u4.w;
    }
    ap += __shfl_xor_sync(0xffffffffu, ap, 8);
    ap += __shfl_xor_sync(0xffffffffu, ap, 16);
    const float oobs = -(ap + cconst[0]) * SCALE;

    float s[25];
    #pragma unroll
    for (int t = 0; t < 25; t++) {
        const int dy = t / 5 - 2, dx = t % 5 - 2;
        const int ny = gy + dy, nx = gx + dx;
        if ((unsigned)ny < (unsigned)HW && (unsigned)nx < (unsigned)HW) {
            const int r = ly + dy + 2, cc = lx + dx + 2;
            const float* yp = &sm[(r * 36 + cc) * AT_SY_PX + sub * 32];
            float d = 0.f;
            #pragma unroll
            for (int i = 0; i < 8; i++) {
                float4 yv = *(const float4*)&yp[i * 4];
                d += xr[i].x * yv.x + xr[i].y * yv.y + xr[i].z * yv.z + xr[i].w * yv.w;
            }
            d += __shfl_xor_sync(0xffffffffu, d, 8);
            d += __shfl_xor_sync(0xffffffffu, d, 16);
            s[t] = (d + sm[AT_OFF_SB + r * 36 + cc]) * SCALE;
        } else {
            s[t] = oobs;
        }
    }

    float mx = s[0];
    #pragma unroll
    for (int t = 1; t < 25; t++) mx = fmaxf(mx, s[t]);
    float sum = 0.f;
    #pragma unroll
    for (int t = 0; t < 25; t++) { s[t] = expf(s[t] - mx); sum += s[t]; }

    if (sub == 0) {
        float inv = 1.f / sum;
        float c0 = 0.f, c1 = 0.f;
        #pragma unroll
        for (int t = 0; t < 25; t++) {
            const int dy = t / 5 - 2, dx = t % 5 - 2;
            const int ny = gy + dy, nx = gx + dx;
            if ((unsigned)ny < (unsigned)HW && (unsigned)nx < (unsigned)HW) {
                const int r = ly + dy + 2, cc = lx + dx + 2;
                float w = s[t] * inv;
                c0 += w * sm[AT_OFF_SF + r * 36 + cc];
                c1 += w * sm[AT_OFF_SF + 216 + r * 36 + cc];
            }
        }
        fi[(size_t)(b * 2 + 0) * NPIX + gy * HW + gx] = c0;
        fi[(size_t)(b * 2 + 1) * NPIX + gy * HW + gx] = c1;
    }
}

// ---------------- small utility kernels ----------------
__global__ void copy_kernel(float* __restrict__ dst, const float* __restrict__ src, int n) {
    int i = blockIdx.x * 256 + threadIdx.x;
    if (i < n) dst[i] = src[i];
}

// pack hcat = [feat0 | warp(feat1, flow) | flow] NCHW
__global__ __launch_bounds__(128) void pack_kernel(
    const float* __restrict__ feat0, const float* __restrict__ feat1,
    const float* __restrict__ flow, float* __restrict__ hcat)
{
    const int x = threadIdx.x;
    const int y = blockIdx.x;
    const int b = blockIdx.y;
    const int here = y * HW + x;

    float fx = flow[(b * 2 + 0) * NPIX + here];
    float fy = flow[(b * 2 + 1) * NPIX + here];
    float xs = fminf(fmaxf((float)x + fx, 0.f), 127.f);
    float ys = fminf(fmaxf((float)y + fy, 0.f), 127.f);
    float x0f = floorf(xs), y0f = floorf(ys);
    int ix0 = (int)x0f, iy0 = (int)y0f;
    int ix1 = min(ix0 + 1, 127), iy1 = min(iy0 + 1, 127);
    float wx = xs - x0f, wy = ys - y0f;
    float w00 = (1.f - wx) * (1.f - wy), w01 = wx * (1.f - wy);
    float w10 = (1.f - wx) * wy,         w11 = wx * wy;
    int o00 = iy0 * HW + ix0, o01 = iy0 * HW + ix1;
    int o10 = iy1 * HW + ix0, o11 = iy1 * HW + ix1;

    float* hb = hcat + (size_t)b * 258 * NPIX;
    const float* f0 = feat0 + (size_t)b * CH * NPIX;
    const float* f1 = feat1 + (size_t)b * CH * NPIX;

    for (int c = 0; c < CH; c++) {
        hb[(size_t)c * NPIX + here] = f0[(size_t)c * NPIX + here];
        const float* p = f1 + (size_t)c * NPIX;
        hb[(size_t)(CH + c) * NPIX + here] =
            w00 * p[o00] + w01 * p[o01] + w10 * p[o10] + w11 * p[o11];
    }
    hb[(size_t)256 * NPIX + here] = fx;
    hb[(size_t)257 * NPIX + here] = fy;
}

// ---------------- host orchestration ----------------
static float* sym_addr(const void* symbol) {
    void* p = nullptr;
    cudaGetSymbolAddress(&p, symbol);
    return (float*)p;
}

extern "C" void kernel_launch(void* const* d_in, const int* in_sizes, int n_in,
                              void* d_out, int out_size)
{
    (void)in_sizes; (void)n_in; (void)out_size;
    const float* feat0     = (const float*)d_in[0];
    const float* feat1     = (const float*)d_in[1];
    const float* flow_init = (const float*)d_in[2];
    const float* lc_w1 = (const float*)d_in[3];
    const float* lc_b1 = (const float*)d_in[4];
    const float* lc_w2 = (const float*)d_in[5];
    const float* lc_b2 = (const float*)d_in[6];
    const float* qw    = (const float*)d_in[7];
    const float* qb    = (const float*)d_in[8];
    const float* kw    = (const float*)d_in[9];
    const float* kb    = (const float*)d_in[10];
    const float* fr_w1 = (const float*)d_in[11];
    const float* fr_b1 = (const float*)d_in[12];
    const float* fr_w2 = (const float*)d_in[13];
    const float* fr_b2 = (const float*)d_in[14];
    const float* fr_w3 = (const float*)d_in[15];
    const float* fr_b3 = (const float*)d_in[16];
    const float* cf_w1 = (const float*)d_in[17];
    const float* cf_b1 = (const float*)d_in[18];
    const float* cf_w2 = (const float*)d_in[19];
    const float* cf_b2 = (const float*)d_in[20];
    const float* cf_w3 = (const float*)d_in[21];
    const float* cf_b3 = (const float*)d_in[22];

    float* lf0   = sym_addr(g_lf0);
    float* lf1   = sym_addr(g_lf1);
    float* tmp   = sym_addr(g_tmp);
    float* tmp2  = sym_addr(g_tmp2);
    float* xbuf  = sym_addr(g_x);
    float* ybuf  = sym_addr(g_y);
    float* flow  = sym_addr(g_flow);
    float* fi    = sym_addr(g_fi);
    float* hcat  = sym_addr(g_hcat);
    float* h2    = sym_addr(g_h2);
    float* Mbuf  = sym_addr(g_M);
    float* ubuf  = sym_addr(g_u);
    float* bvbuf = sym_addr(g_bv);
    float* cbuf  = sym_addr(g_c);
    float* bscal = sym_addr(g_bscal);
    float* out_flow = (float*)d_out;
    float* out_conf = (float*)d_out + BATCH * 2 * NPIX;

    cudaFuncSetAttribute(fr_fused_kernel,
                         cudaFuncAttributeMaxDynamicSharedMemorySize, FR_SMEM_BYTES);
    cudaFuncSetAttribute(attn_tiled_kernel,
                         cudaFuncAttributeMaxDynamicSharedMemorySize, AT_SMEM_BYTES);

    // one-time prep of the fused attention matrices
    prepM_kernel<<<128, 128>>>(qw, kw, Mbuf);
    prepUV_kernel<<<1, 128>>>(qw, kw, qb, kb, ubuf, bvbuf, cbuf);

    const dim3 cblk(256);
    // local_conv on both features, merged launches
    conv3x3_kernel<16><<<dim3(4,4,2*BATCH*8), cblk>>>(feat0, feat1, lc_w1, lc_b1, tmp, tmp2, 128, 128, ACT_GELU);
    conv3x3_kernel<16><<<dim3(4,4,2*BATCH*8), cblk>>>(tmp,   tmp2,  lc_w2, lc_b2, lf0, lf1,  128, 128, ACT_NONE);

    copy_kernel<<<(BATCH*2*NPIX + 255)/256, 256>>>(flow, flow_init, BATCH*2*NPIX);

    for (int it = 0; it < ITERS; ++it) {
        warp_diff_kernel<<<dim3(2*HW, BATCH), 128>>>(lf0, lf1, flow, xbuf);
        gemm_y_kernel<<<BATCH*NPIX/128, 256>>>(xbuf, Mbuf, bvbuf, ybuf, bscal);
        attn_tiled_kernel<<<dim3(4, 64, BATCH), 256, AT_SMEM_BYTES>>>(
            xbuf, ybuf, bscal, ubuf, cbuf, flow, fi);
        fr_fused_kernel<<<dim3(8,8,BATCH), 256, FR_SMEM_BYTES>>>(
            fi, fr_w1, fr_b1, fr_w2, fr_b2, fr_w3, fr_b3, flow);
    }

    // confidence head
    pack_kernel<<<dim3(HW, BATCH), 128>>>(feat0, feat1, flow, hcat);
    conv3x3_kernel<16><<<dim3(4,4,BATCH*8), cblk>>>(hcat, hcat, cf_w1, cf_b1, tmp, tmp, 258, 128, ACT_GELU);
    conv3x3_kernel<16><<<dim3(4,4,BATCH*4), cblk>>>(tmp,  tmp,  cf_w2, cf_b2, h2,  h2,  128, 64,  ACT_GELU);
    conv3x3_kernel<2><<<dim3(4,4,BATCH),  cblk>>>(h2, h2, cf_w3, cf_b3, out_conf, out_conf, 64, 1, ACT_SIGM);

    copy_kernel<<<(BATCH*2*NPIX + 255)/256, 256>>>(out_flow, flow, BATCH*2*NPIX);
}

// round 9
// speedup vs baseline: 2.0672x; 1.3008x over previous
#include <cuda_runtime.h>
#include <stdint.h>
#include <math.h>

#define HW     128
#define BATCH  2
#define CH     128
#define NPIX   (HW*HW)            // 16384
#define ITERS  10

#define NT_LC   16384             // 4 images x 4096 tiles (2 feats x 2 batch)
#define NT_CF   8192              // 2 images
#define VPL_LC  (128*16384)
#define VPL_CF  (264*8192)
#define MPL_LC  (128*16384)
#define MPL_CF  (128*8192)

// ---------------- scratch (static device allocations; no cudaMalloc) ----------------
__device__ float g_lf0 [BATCH*CH*NPIX];
__device__ float g_lf1 [BATCH*CH*NPIX];
__device__ float g_tmp [BATCH*CH*NPIX];
__device__ float g_tmp2[BATCH*CH*NPIX];
__device__ float g_x   [BATCH*NPIX*CH];
__device__ float g_y   [BATCH*NPIX*CH];
__device__ float g_flow[BATCH*2*NPIX];
__device__ float g_fi  [BATCH*2*NPIX];
__device__ float g_hcat[BATCH*258*NPIX];
__device__ float g_h2  [BATCH*64*NPIX];
__device__ float g_M   [CH*CH];
__device__ float g_u   [CH];
__device__ float g_bv  [CH];
__device__ float g_c   [1];
__device__ float g_bscal[BATCH*NPIX];
// Winograd buffers
__device__ float g_V  [16 * VPL_CF];         // max(16*VPL_LC, 16*VPL_CF) = 16*VPL_CF
__device__ float g_Mw [16 * MPL_LC];
__device__ float g_U1 [16 * 128 * 128];
__device__ float g_U2 [16 * 128 * 128];
__device__ float g_Uc [16 * 264 * 128];

// ---------------- helpers ----------------
__device__ __forceinline__ float gelu_f(float v) {
    return 0.5f * v * (1.0f + erff(v * 0.70710678118654752f));
}
__device__ __forceinline__ float sigmoid_f(float v) {
    return 1.0f / (1.0f + expf(-v));
}

#define ACT_NONE 0
#define ACT_GELU 1
#define ACT_SIGM 2

// ---------------- prep: M = Wq^T Wk ; u = Wq^T kb ; bv = Wk^T qb ; c = qb.kb ----------------
__global__ void prepM_kernel(const float* __restrict__ qw, const float* __restrict__ kw,
                             float* __restrict__ M)
{
    int i = blockIdx.x, j = threadIdx.x;
    float s = 0.f;
    for (int d = 0; d < CH; d++)
        s += qw[d * CH + i] * kw[d * CH + j];
    M[i * CH + j] = s;
}

__global__ void prepUV_kernel(const float* __restrict__ qw, const float* __restrict__ kw,
                              const float* __restrict__ qb, const float* __restrict__ kb,
                              float* __restrict__ u, float* __restrict__ bv, float* __restrict__ c)
{
    int j = threadIdx.x;
    float su = 0.f, sb = 0.f;
    for (int d = 0; d < CH; d++) {
        su += qw[d * CH + j] * kb[d];
        sb += kw[d * CH + j] * qb[d];
    }
    u[j] = su;
    bv[j] = sb;
    if (j == 0) {
        float cc = 0.f;
        for (int d = 0; d < CH; d++) cc += qb[d] * kb[d];
        c[0] = cc;
    }
}

// ---------------- Winograd F(2x2,3x3) ----------------
// weight transform: U[t][cin][cout] = (G g G^T), t = r*4+c
__global__ void wino_wt_kernel(const float* __restrict__ w, float* __restrict__ U,
                               int Cin, int CinPad, int Cout)
{
    int i = blockIdx.x * 256 + threadIdx.x;
    if (i >= CinPad * Cout) return;
    int ci = i / Cout, co = i % Cout;
    float g[3][3];
    #pragma unroll
    for (int r = 0; r < 3; r++)
        #pragma unroll
        for (int cc = 0; cc < 3; cc++)
            g[r][cc] = (ci < Cin) ? w[((size_t)co * Cin + ci) * 9 + r * 3 + cc] : 0.f;
    float t[4][3];
    #pragma unroll
    for (int cc = 0; cc < 3; cc++) {
        t[0][cc] = g[0][cc];
        t[1][cc] = 0.5f * (g[0][cc] + g[1][cc] + g[2][cc]);
        t[2][cc] = 0.5f * (g[0][cc] - g[1][cc] + g[2][cc]);
        t[3][cc] = g[2][cc];
    }
    float u4[4][4];
    #pragma unroll
    for (int r = 0; r < 4; r++) {
        u4[r][0] = t[r][0];
        u4[r][1] = 0.5f * (t[r][0] + t[r][1] + t[r][2]);
        u4[r][2] = 0.5f * (t[r][0] - t[r][1] + t[r][2]);
        u4[r][3] = t[r][2];
    }
    #pragma unroll
    for (int r = 0; r < 4; r++)
        #pragma unroll
        for (int cc = 0; cc < 4; cc++)
            U[(size_t)(r * 4 + cc) * CinPad * Cout + (size_t)ci * Cout + co] = u4[r][cc];
}

// input transform: V[t][ci][tile], tile = img*4096 + ty*64 + tx; img<2 -> srcA(b=img), else srcB(b=img-2)
__global__ __launch_bounds__(256) void wino_in_kernel(
    const float* __restrict__ srcA, const float* __restrict__ srcB,
    float* __restrict__ V, int Cin, int CinPad, int NT, int vplane)
{
    const int tg = blockIdx.x * 32 + (threadIdx.x & 31);
    const int ci = blockIdx.y * 8 + (threadIdx.x >> 5);
    const int img = tg >> 12;
    const int within = tg & 4095;
    const int ty = within >> 6, tx = within & 63;
    const float* src = (img < 2) ? srcA : srcB;
    const int b = img & 1;

    float d[4][4];
    if (ci < Cin) {
        const float* p = src + (size_t)(b * Cin + ci) * NPIX;
        const int yb = 2 * ty - 1, xb = 2 * tx - 1;
        #pragma unroll
        for (int r = 0; r < 4; r++) {
            int yy = yb + r;
            #pragma unroll
            for (int cc = 0; cc < 4; cc++) {
                int xx = xb + cc;
                d[r][cc] = ((unsigned)yy < (unsigned)HW && (unsigned)xx < (unsigned)HW)
                         ? p[yy * HW + xx] : 0.f;
            }
        }
    } else {
        #pragma unroll
        for (int r = 0; r < 4; r++)
            #pragma unroll
            for (int cc = 0; cc < 4; cc++) d[r][cc] = 0.f;
    }

    float tm[4][4];
    #pragma unroll
    for (int j = 0; j < 4; j++) {
        tm[0][j] = d[0][j] - d[2][j];
        tm[1][j] = d[1][j] + d[2][j];
        tm[2][j] = d[2][j] - d[1][j];
        tm[3][j] = d[1][j] - d[3][j];
    }
    float v4[4][4];
    #pragma unroll
    for (int i = 0; i < 4; i++) {
        v4[i][0] = tm[i][0] - tm[i][2];
        v4[i][1] = tm[i][1] + tm[i][2];
        v4[i][2] = tm[i][2] - tm[i][1];
        v4[i][3] = tm[i][1] - tm[i][3];
    }
    #pragma unroll
    for (int r = 0; r < 4; r++)
        #pragma unroll
        for (int cc = 0; cc < 4; cc++)
            V[(size_t)(r * 4 + cc) * vplane + (size_t)ci * NT + tg] = v4[r][cc];
}

// per-t GEMM: Mw[t][co][tile] = sum_ci U[t][ci][co] * V[t][ci][tile]   (Cout = 128 fixed)
__global__ __launch_bounds__(256) void wino_gemm_kernel(
    const float* __restrict__ U, const float* __restrict__ V, float* __restrict__ Mw,
    int CinPad, int NT, int uplane, int vplane, int mplane)
{
    __shared__ float As[8][132];
    __shared__ float Bs[8][132];

    const int tid = threadIdx.x;
    const int tx = tid & 15, ty = tid >> 4;
    const int t16 = blockIdx.y;
    const int n0 = blockIdx.x * 128;
    const float* Ut = U + (size_t)t16 * uplane;
    const float* Vt = V + (size_t)t16 * vplane;
    float* Mt = Mw + (size_t)t16 * mplane;

    float acc[8][8];
    #pragma unroll
    for (int i = 0; i < 8; i++)
        #pragma unroll
        for (int j = 0; j < 8; j++) acc[i][j] = 0.f;

    const int krow = tid >> 5;        // 0..7
    const int col4 = (tid & 31) * 4;  // 0..124

    for (int k0 = 0; k0 < CinPad; k0 += 8) {
        float4 a = *(const float4*)&Ut[(size_t)(k0 + krow) * 128 + col4];
        float4 b = *(const float4*)&Vt[(size_t)(k0 + krow) * NT + n0 + col4];
        *(float4*)&As[krow][col4] = a;
        *(float4*)&Bs[krow][col4] = b;
        __syncthreads();
        #pragma unroll
        for (int k = 0; k < 8; k++) {
            float af[8], bf[8];
            *(float4*)&af[0] = *(const float4*)&As[k][ty * 8];
            *(float4*)&af[4] = *(const float4*)&As[k][ty * 8 + 4];
            *(float4*)&bf[0] = *(const float4*)&Bs[k][tx * 8];
            *(float4*)&bf[4] = *(const float4*)&Bs[k][tx * 8 + 4];
            #pragma unroll
            for (int i = 0; i < 8; i++)
                #pragma unroll
                for (int j = 0; j < 8; j++)
                    acc[i][j] += af[i] * bf[j];
        }
        __syncthreads();
    }

    #pragma unroll
    for (int i = 0; i < 8; i++) {
        float* row = Mt + (size_t)(ty * 8 + i) * NT + n0 + tx * 8;
        *(float4*)&row[0] = *(float4*)&acc[i][0];
        *(float4*)&row[4] = *(float4*)&acc[i][4];
    }
}

// inverse transform + bias + act -> NCHW dst
__global__ __launch_bounds__(256) void wino_out_kernel(
    const float* __restrict__ Mw, const float* __restrict__ bias,
    float* __restrict__ dstA, float* __restrict__ dstB,
    int Cout, int NT, int mplane, int act)
{
    const int tg = blockIdx.x * 32 + (threadIdx.x & 31);
    const int co = blockIdx.y * 8 + (threadIdx.x >> 5);
    const int img = tg >> 12;
    const int within = tg & 4095;
    const int ty = within >> 6, tx = within & 63;
    float* dst = (img < 2) ? dstA : dstB;
    const int b = img & 1;

    float m[4][4];
    #pragma unroll
    for (int r = 0; r < 4; r++)
        #pragma unroll
        for (int cc = 0; cc < 4; cc++)
            m[r][cc] = Mw[(size_t)(r * 4 + cc) * mplane + (size_t)co * NT + tg];

    float s[2][4];
    #pragma unroll
    for (int j = 0; j < 4; j++) {
        s[0][j] = m[0][j] + m[1][j] + m[2][j];
        s[1][j] = m[1][j] - m[2][j] - m[3][j];
    }
    float bvv = bias[co];
    float y00 = s[0][0] + s[0][1] + s[0][2] + bvv;
    float y01 = s[0][1] - s[0][2] - s[0][3] + bvv;
    float y10 = s[1][0] + s[1][1] + s[1][2] + bvv;
    float y11 = s[1][1] - s[1][2] - s[1][3] + bvv;
    if (act == ACT_GELU) {
        y00 = gelu_f(y00); y01 = gelu_f(y01); y10 = gelu_f(y10); y11 = gelu_f(y11);
    }
    float* q = dst + (size_t)(b * Cout + co) * NPIX + (2 * ty) * HW + 2 * tx;
    q[0] = y00; q[1] = y01; q[HW] = y10; q[HW + 1] = y11;
}

// ---------------- direct NCHW 3x3 conv (cf2 / cf3) ----------------
template<int COT>
__global__ __launch_bounds__(256, 2) void conv3x3_kernel(
    const float* __restrict__ in, const float* __restrict__ wgt,
    const float* __restrict__ bias, float* __restrict__ out,
    int Cin, int Cout, int act)
{
    __shared__ float s_in[8][34][34];
    __shared__ __align__(16) float s_w[8][COT][12];

    const int tid = threadIdx.x;
    const int tx = tid & 15, ty = tid >> 4;
    const int x0 = blockIdx.x * 32, y0 = blockIdx.y * 32;
    const int nco = (Cout + COT - 1) / COT;
    const int bb  = blockIdx.z / nco;
    const int co0 = (blockIdx.z % nco) * COT;

    float acc[COT][2][2];
    #pragma unroll
    for (int c = 0; c < COT; c++)
        #pragma unroll
        for (int i = 0; i < 2; i++)
            #pragma unroll
            for (int j = 0; j < 2; j++) acc[c][i][j] = 0.f;

    for (int c0 = 0; c0 < Cin; c0 += 8) {
        for (int idx = tid; idx < 8 * 1156; idx += 256) {
            int ci = idx / 1156;
            int r  = (idx % 1156) / 34;
            int cc = idx % 34;
            int gy = y0 - 1 + r, gx = x0 - 1 + cc;
            int cin = c0 + ci;
            float v = 0.f;
            if (cin < Cin && (unsigned)gy < (unsigned)HW && (unsigned)gx < (unsigned)HW)
                v = in[((size_t)(bb * Cin + cin) * HW + gy) * HW + gx];
            s_in[ci][r][cc] = v;
        }
        for (int idx = tid; idx < 8 * COT * 9; idx += 256) {
            int ci = idx / (COT * 9);
            int co = (idx % (COT * 9)) / 9;
            int k  = idx % 9;
            int cin = c0 + ci, cog = co0 + co;
            float v = 0.f;
            if (cin < Cin && cog < Cout)
                v = wgt[((size_t)cog * Cin + cin) * 9 + k];
            s_w[ci][co][k] = v;
        }
        __syncthreads();

        #pragma unroll
        for (int ci = 0; ci < 8; ci++) {
            float v[4][4];
            #pragma unroll
            for (int i = 0; i < 4; i++) {
                float2 a = *(const float2*)&s_in[ci][ty * 2 + i][tx * 2];
                float2 b = *(const float2*)&s_in[ci][ty * 2 + i][tx * 2 + 2];
                v[i][0] = a.x; v[i][1] = a.y; v[i][2] = b.x; v[i][3] = b.y;
            }
            #pragma unroll
            for (int co = 0; co < COT; co++) {
                float4 wa = *(const float4*)&s_w[ci][co][0];
                float4 wb = *(const float4*)&s_w[ci][co][4];
                float w8  = s_w[ci][co][8];
                #pragma unroll
                for (int i2 = 0; i2 < 2; i2++)
                    #pragma unroll
                    for (int j2 = 0; j2 < 2; j2++) {
                        float a = acc[co][i2][j2];
                        a += v[i2+0][j2+0] * wa.x;
                        a += v[i2+0][j2+1] * wa.y;
                        a += v[i2+0][j2+2] * wa.z;
                        a += v[i2+1][j2+0] * wa.w;
                        a += v[i2+1][j2+1] * wb.x;
                        a += v[i2+1][j2+2] * wb.y;
                        a += v[i2+2][j2+0] * wb.z;
                        a += v[i2+2][j2+1] * wb.w;
                        a += v[i2+2][j2+2] * w8;
                        acc[co][i2][j2] = a;
                    }
            }
        }
        __syncthreads();
    }

    #pragma unroll
    for (int co = 0; co < COT; co++) {
        int cog = co0 + co;
        if (cog >= Cout) break;
        float bvv = bias[cog];
        #pragma unroll
        for (int i2 = 0; i2 < 2; i2++)
            #pragma unroll
            for (int j2 = 0; j2 < 2; j2++) {
                int oy = y0 + ty * 2 + i2, ox = x0 + tx * 2 + j2;
                float v = acc[co][i2][j2] + bvv;
                if (act == ACT_GELU) v = gelu_f(v);
                else if (act == ACT_SIGM) v = sigmoid_f(v);
                out[((size_t)(bb * Cout + cog) * HW + oy) * HW + ox] = v;
            }
    }
}

// ---------------- fused flow-refiner chain ----------------
#define FR_OFF_W1 0
#define FR_OFF_B1 288
#define FR_OFF_W2 304
#define FR_OFF_B2 2608
#define FR_OFF_W3 2624
#define FR_OFF_B3 2912
#define FR_OFF_FI 2916
#define FR_OFF_T1 3884
#define FR_OFF_T2 10284
#define FR_SMEM_FLOATS 15468
#define FR_SMEM_BYTES (FR_SMEM_FLOATS * 4)

__global__ __launch_bounds__(256) void fr_fused_kernel(
    const float* __restrict__ fi,
    const float* __restrict__ w1, const float* __restrict__ b1,
    const float* __restrict__ w2, const float* __restrict__ b2,
    const float* __restrict__ w3, const float* __restrict__ b3,
    float* __restrict__ flow)
{
    extern __shared__ float sm[];
    const int tid = threadIdx.x;
    const int x0 = blockIdx.x * 16, y0 = blockIdx.y * 16;
    const int b = blockIdx.z;

    for (int u = tid; u < 288;  u += 256) sm[FR_OFF_W1 + u] = w1[u];
    for (int u = tid; u < 16;   u += 256) sm[FR_OFF_B1 + u] = b1[u];
    for (int u = tid; u < 2304; u += 256) sm[FR_OFF_W2 + u] = w2[u];
    for (int u = tid; u < 16;   u += 256) sm[FR_OFF_B2 + u] = b2[u];
    for (int u = tid; u < 288;  u += 256) sm[FR_OFF_W3 + u] = w3[u];
    for (int u = tid; u < 2;    u += 256) sm[FR_OFF_B3 + u] = b3[u];
    for (int u = tid; u < 2 * 484; u += 256) {
        int ci = u / 484;
        int rem = u % 484;
        int r = rem / 22, c = rem % 22;
        int gy = y0 - 3 + r, gx = x0 - 3 + c;
        float v = 0.f;
        if ((unsigned)gy < (unsigned)HW && (unsigned)gx < (unsigned)HW)
            v = fi[(size_t)(b * 2 + ci) * NPIX + gy * HW + gx];
        sm[FR_OFF_FI + u] = v;
    }
    __syncthreads();

    for (int u = tid; u < 16 * 400; u += 256) {
        int co = u / 400;
        int rem = u % 400;
        int r = rem / 20, c = rem % 20;
        int gy = y0 - 2 + r, gx = x0 - 2 + c;
        float v = 0.f;
        if ((unsigned)gy < (unsigned)HW && (unsigned)gx < (unsigned)HW) {
            float s = sm[FR_OFF_B1 + co];
            #pragma unroll
            for (int ci = 0; ci < 2; ci++)
                #pragma unroll
                for (int dy = 0; dy < 3; dy++)
                    #pragma unroll
                    for (int dx = 0; dx < 3; dx++)
                        s += sm[FR_OFF_FI + (ci * 22 + r + dy) * 22 + c + dx]
                           * sm[FR_OFF_W1 + (co * 2 + ci) * 9 + dy * 3 + dx];
            v = gelu_f(s);
        }
        sm[FR_OFF_T1 + u] = v;
    }
    __syncthreads();

    for (int u = tid; u < 16 * 324; u += 256) {
        int co = u / 324;
        int rem = u % 324;
        int r = rem / 18, c = rem % 18;
        int gy = y0 - 1 + r, gx = x0 - 1 + c;
        float v = 0.f;
        if ((unsigned)gy < (unsigned)HW && (unsigned)gx < (unsigned)HW) {
            float s = sm[FR_OFF_B2 + co];
            #pragma unroll
            for (int ci = 0; ci < 16; ci++) {
                const float* t1p = &sm[FR_OFF_T1 + (ci * 20 + r) * 20 + c];
                const float* wp  = &sm[FR_OFF_W2 + (co * 16 + ci) * 9];
                s += t1p[0]  * wp[0] + t1p[1]  * wp[1] + t1p[2]  * wp[2];
                s += t1p[20] * wp[3] + t1p[21] * wp[4] + t1p[22] * wp[5];
                s += t1p[40] * wp[6] + t1p[41] * wp[7] + t1p[42] * wp[8];
            }
            v = gelu_f(s);
        }
        sm[FR_OFF_T2 + u] = v;
    }
    __syncthreads();

    for (int u = tid; u < 2 * 256; u += 256) {
        int f = u / 256;
        int rem = u % 256;
        int r = rem / 16, c = rem % 16;
        float s = sm[FR_OFF_B3 + f];
        #pragma unroll
        for (int ci = 0; ci < 16; ci++) {
            const float* t2p = &sm[FR_OFF_T2 + (ci * 18 + r) * 18 + c];
            const float* wp  = &sm[FR_OFF_W3 + (f * 16 + ci) * 9];
            s += t2p[0]  * wp[0] + t2p[1]  * wp[1] + t2p[2]  * wp[2];
            s += t2p[18] * wp[3] + t2p[19] * wp[4] + t2p[20] * wp[5];
            s += t2p[36] * wp[6] + t2p[37] * wp[7] + t2p[38] * wp[8];
        }
        int gy = y0 + r, gx = x0 + c;
        flow[(size_t)(b * 2 + f) * NPIX + gy * HW + gx] += s;
    }
}

// ---------------- warp + diff + L2-normalize; x = 1 - diffn channel-last ----------------
__global__ __launch_bounds__(128) void warp_diff_kernel(
    const float* __restrict__ lf0, const float* __restrict__ lf1,
    const float* __restrict__ flow, float* __restrict__ xout)
{
    __shared__ float s_diff[64][129];
    __shared__ float s_ssq[128];
    __shared__ float s_rinv[64];

    const int tid = threadIdx.x;
    const int b = blockIdx.y;
    const int y = blockIdx.x >> 1;
    const int xbase = (blockIdx.x & 1) * 64;
    const int px = tid & 63;
    const int half = tid >> 6;
    const int x = xbase + px;

    float fx = flow[(b * 2 + 0) * NPIX + y * HW + x];
    float fy = flow[(b * 2 + 1) * NPIX + y * HW + x];
    float xs = fminf(fmaxf((float)x + fx, 0.f), 127.f);
    float ys = fminf(fmaxf((float)y + fy, 0.f), 127.f);
    float x0f = floorf(xs), y0f = floorf(ys);
    int ix0 = (int)x0f, iy0 = (int)y0f;
    int ix1 = min(ix0 + 1, 127), iy1 = min(iy0 + 1, 127);
    float wx = xs - x0f, wy = ys - y0f;
    float w00 = (1.f - wx) * (1.f - wy), w01 = wx * (1.f - wy);
    float w10 = (1.f - wx) * wy,         w11 = wx * wy;
    int o00 = iy0 * HW + ix0, o01 = iy0 * HW + ix1;
    int o10 = iy1 * HW + ix0, o11 = iy1 * HW + ix1;

    const float* lf1b = lf1 + (size_t)b * CH * NPIX;
    const float* lf0b = lf0 + (size_t)b * CH * NPIX;
    const int here = y * HW + x;

    float ssq = 0.f;
    for (int c = half * 64; c < half * 64 + 64; ++c) {
        const float* p = lf1b + (size_t)c * NPIX;
        float wv = w00 * p[o00] + w01 * p[o01] + w10 * p[o10] + w11 * p[o11];
        float d = lf0b[(size_t)c * NPIX + here] - wv;
        s_diff[px][c] = d;
        ssq += d * d;
    }
    s_ssq[tid] = ssq;
    __syncthreads();
    if (tid < 64) {
        float s = s_ssq[tid] + s_ssq[tid + 64];
        s_rinv[tid] = 1.f / fmaxf(sqrtf(s), 1e-12f);
    }
    __syncthreads();

    float* xb = xout + ((size_t)b * NPIX + y * HW + xbase) * CH;
    for (int p2 = 0; p2 < 64; ++p2)
        xb[(size_t)p2 * CH + tid] = 1.f - s_diff[p2][tid] * s_rinv[p2];
}

// ---------------- y = M x + bscal = bv.x ----------------
__global__ __launch_bounds__(256) void gemm_y_kernel(
    const float* __restrict__ X, const float* __restrict__ M,
    const float* __restrict__ bv,
    float* __restrict__ Y, float* __restrict__ bscal)
{
    __shared__ float As[8][132];
    __shared__ float Bs[8][132];
    __shared__ float sbv[128];

    const int tid = threadIdx.x;
    const int tx = tid & 15, ty = tid >> 4;
    const int m0 = blockIdx.x * 128;

    if (tid < 128) sbv[tid] = bv[tid];
    __syncthreads();

    float acc[8][8];
    #pragma unroll
    for (int i = 0; i < 8; i++)
        #pragma unroll
        for (int j = 0; j < 8; j++) acc[i][j] = 0.f;

    const int row  = tid >> 1;
    const int part = tid & 1;
    float bdot = 0.f;

    for (int kk = 0; kk < 128; kk += 8) {
        float4 a = *(const float4*)&X[(size_t)(m0 + row) * 128 + kk + part * 4];
        float4 b = *(const float4*)&M[(size_t)row * 128 + kk + part * 4];
        int kb4 = kk + part * 4;
        bdot += a.x * sbv[kb4+0] + a.y * sbv[kb4+1] + a.z * sbv[kb4+2] + a.w * sbv[kb4+3];
        As[part*4+0][row] = a.x; As[part*4+1][row] = a.y;
        As[part*4+2][row] = a.z; As[part*4+3][row] = a.w;
        Bs[part*4+0][row] = b.x; Bs[part*4+1][row] = b.y;
        Bs[part*4+2][row] = b.z; Bs[part*4+3][row] = b.w;
        __syncthreads();
        #pragma unroll
        for (int k = 0; k < 8; k++) {
            float af[8], bf[8];
            *(float4*)&af[0] = *(const float4*)&As[k][ty * 8];
            *(float4*)&af[4] = *(const float4*)&As[k][ty * 8 + 4];
            *(float4*)&bf[0] = *(const float4*)&Bs[k][tx * 8];
            *(float4*)&bf[4] = *(const float4*)&Bs[k][tx * 8 + 4];
            #pragma unroll
            for (int i = 0; i < 8; i++)
                #pragma unroll
                for (int j = 0; j < 8; j++)
                    acc[i][j] += af[i] * bf[j];
        }
        __syncthreads();
    }

    float other = __shfl_xor_sync(0xffffffffu, bdot, 1);
    if (part == 0) bscal[m0 + row] = bdot + other;

    #pragma unroll
    for (int i = 0; i < 8; i++) {
        int m = m0 + ty * 8 + i;
        #pragma unroll
        for (int j = 0; j < 8; j++)
            Y[(size_t)m * 128 + tx * 8 + j] = acc[i][j];
    }
}

// ---------------- smem-tiled 25-tap local attention ----------------
#define AT_SY_PX 132
#define AT_OFF_SX (6*36*AT_SY_PX)
#define AT_OFF_SB (AT_OFF_SX + 2*32*AT_SY_PX)
#define AT_OFF_SF (AT_OFF_SB + 216)
#define AT_SMEM_FLOATS (AT_OFF_SF + 432)
#define AT_SMEM_BYTES (AT_SMEM_FLOATS * 4)

__global__ __launch_bounds__(256) void attn_tiled_kernel(
    const float* __restrict__ X, const float* __restrict__ Y,
    const float* __restrict__ bscal, const float* __restrict__ uvec,
    const float* __restrict__ cconst,
    const float* __restrict__ flow, float* __restrict__ fi)
{
    extern __shared__ float sm[];
    const float SCALE = 0.08838834764831845f;
    const int tid = threadIdx.x;
    const int x0 = blockIdx.x * 32;
    const int y0 = blockIdx.y * 2;
    const int b  = blockIdx.z;
    const int base = b << 14;

    for (int i = tid; i < 6 * 36 * 32; i += 256) {
        int pos = i >> 5, c4 = (i & 31) * 4;
        int r = pos / 36, cc = pos % 36;
        int gy = y0 - 2 + r, gx = x0 - 2 + cc;
        float4 v = make_float4(0.f, 0.f, 0.f, 0.f);
        if ((unsigned)gy < (unsigned)HW && (unsigned)gx < (unsigned)HW)
            v = *(const float4*)&Y[((size_t)(base + gy * HW + gx)) * 128 + c4];
        *(float4*)&sm[(r * 36 + cc) * AT_SY_PX + c4] = v;
    }
    for (int i = tid; i < 2 * 32 * 32; i += 256) {
        int pos = i >> 5, c4 = (i & 31) * 4;
        int py = pos >> 5, px = pos & 31;
        float4 v = *(const float4*)&X[((size_t)(base + (y0 + py) * HW + x0 + px)) * 128 + c4];
        *(float4*)&sm[AT_OFF_SX + (py * 32 + px) * AT_SY_PX + c4] = v;
    }
    for (int i = tid; i < 216; i += 256) {
        int r = i / 36, cc = i % 36;
        int gy = y0 - 2 + r, gx = x0 - 2 + cc;
        bool ok = ((unsigned)gy < (unsigned)HW) && ((unsigned)gx < (unsigned)HW);
        int n = base + gy * HW + gx;
        sm[AT_OFF_SB + i]       = ok ? bscal[n] : 0.f;
        sm[AT_OFF_SF + i]       = ok ? flow[(size_t)(b * 2 + 0) * NPIX + gy * HW + gx] : 0.f;
        sm[AT_OFF_SF + 216 + i] = ok ? flow[(size_t)(b * 2 + 1) * NPIX + gy * HW + gx] : 0.f;
    }
    __syncthreads();

    const int lane = tid & 31;
    const int warp = tid >> 5;
    const int sub  = lane >> 3;
    const int pxl  = warp * 8 + (lane & 7);
    const int ly = pxl >> 5, lx = pxl & 31;
    const int gy = y0 + ly, gx = x0 + lx;

    float4 xr[8];
    {
        const float* xp = &sm[AT_OFF_SX + (ly * 32 + lx) * AT_SY_PX + sub * 32];
        #pragma unroll
        for (int i = 0; i < 8; i++) xr[i] = *(const float4*)&xp[i * 4];
    }

    float ap = 0.f;
    #pragma unroll
    for (int i = 0; i < 8; i++) {
        const float4 u4 = *(const float4*)&uvec[sub * 32 + i * 4];
        ap += xr[i].x * u4.x + xr[i].y * u4.y + xr[i].z * u4.z + xr[i].w * u4.w;
    }
    ap += __shfl_xor_sync(0xffffffffu, ap, 8);
    ap += __shfl_xor_sync(0xffffffffu, ap, 16);
    const float oobs = -(ap + cconst[0]) * SCALE;

    float s[25];
    #pragma unroll
    for (int t = 0; t < 25; t++) {
        const int dy = t / 5 - 2, dx = t % 5 - 2;
        const int ny = gy + dy, nx = gx + dx;
        if ((unsigned)ny < (unsigned)HW && (unsigned)nx < (unsigned)HW) {
            const int r = ly + dy + 2, cc = lx + dx + 2;
            const float* yp = &sm[(r * 36 + cc) * AT_SY_PX + sub * 32];
            float d = 0.f;
            #pragma unroll
            for (int i = 0; i < 8; i++) {
                float4 yv = *(const float4*)&yp[i * 4];
                d += xr[i].x * yv.x + xr[i].y * yv.y + xr[i].z * yv.z + xr[i].w * yv.w;
            }
            d += __shfl_xor_sync(0xffffffffu, d, 8);
            d += __shfl_xor_sync(0xffffffffu, d, 16);
            s[t] = (d + sm[AT_OFF_SB + r * 36 + cc]) * SCALE;
        } else {
            s[t] = oobs;
        }
    }

    float mx = s[0];
    #pragma unroll
    for (int t = 1; t < 25; t++) mx = fmaxf(mx, s[t]);
    float sum = 0.f;
    #pragma unroll
    for (int t = 0; t < 25; t++) { s[t] = expf(s[t] - mx); sum += s[t]; }

    if (sub == 0) {
        float inv = 1.f / sum;
        float c0 = 0.f, c1 = 0.f;
        #pragma unroll
        for (int t = 0; t < 25; t++) {
            const int dy = t / 5 - 2, dx = t % 5 - 2;
            const int ny = gy + dy, nx = gx + dx;
            if ((unsigned)ny < (unsigned)HW && (unsigned)nx < (unsigned)HW) {
                const int r = ly + dy + 2, cc = lx + dx + 2;
                float w = s[t] * inv;
                c0 += w * sm[AT_OFF_SF + r * 36 + cc];
                c1 += w * sm[AT_OFF_SF + 216 + r * 36 + cc];
            }
        }
        fi[(size_t)(b * 2 + 0) * NPIX + gy * HW + gx] = c0;
        fi[(size_t)(b * 2 + 1) * NPIX + gy * HW + gx] = c1;
    }
}

// ---------------- small utility kernels ----------------
__global__ void copy_kernel(float* __restrict__ dst, const float* __restrict__ src, int n) {
    int i = blockIdx.x * 256 + threadIdx.x;
    if (i < n) dst[i] = src[i];
}

// pack hcat = [feat0 | warp(feat1, flow) | flow] NCHW
__global__ __launch_bounds__(128) void pack_kernel(
    const float* __restrict__ feat0, const float* __restrict__ feat1,
    const float* __restrict__ flow, float* __restrict__ hcat)
{
    const int x = threadIdx.x;
    const int y = blockIdx.x;
    const int b = blockIdx.y;
    const int here = y * HW + x;

    float fx = flow[(b * 2 + 0) * NPIX + here];
    float fy = flow[(b * 2 + 1) * NPIX + here];
    float xs = fminf(fmaxf((float)x + fx, 0.f), 127.f);
    float ys = fminf(fmaxf((float)y + fy, 0.f), 127.f);
    float x0f = floorf(xs), y0f = floorf(ys);
    int ix0 = (int)x0f, iy0 = (int)y0f;
    int ix1 = min(ix0 + 1, 127), iy1 = min(iy0 + 1, 127);
    float wx = xs - x0f, wy = ys - y0f;
    float w00 = (1.f - wx) * (1.f - wy), w01 = wx * (1.f - wy);
    float w10 = (1.f - wx) * wy,         w11 = wx * wy;
    int o00 = iy0 * HW + ix0, o01 = iy0 * HW + ix1;
    int o10 = iy1 * HW + ix0, o11 = iy1 * HW + ix1;

    float* hb = hcat + (size_t)b * 258 * NPIX;
    const float* f0 = feat0 + (size_t)b * CH * NPIX;
    const float* f1 = feat1 + (size_t)b * CH * NPIX;

    for (int c = 0; c < CH; c++) {
        hb[(size_t)c * NPIX + here] = f0[(size_t)c * NPIX + here];
        const float* p = f1 + (size_t)c * NPIX;
        hb[(size_t)(CH + c) * NPIX + here] =
            w00 * p[o00] + w01 * p[o01] + w10 * p[o10] + w11 * p[o11];
    }
    hb[(size_t)256 * NPIX + here] = fx;
    hb[(size_t)257 * NPIX + here] = fy;
}

// ---------------- host orchestration ----------------
static float* sym_addr(const void* symbol) {
    void* p = nullptr;
    cudaGetSymbolAddress(&p, symbol);
    return (float*)p;
}

extern "C" void kernel_launch(void* const* d_in, const int* in_sizes, int n_in,
                              void* d_out, int out_size)
{
    (void)in_sizes; (void)n_in; (void)out_size;
    const float* feat0     = (const float*)d_in[0];
    const float* feat1     = (const float*)d_in[1];
    const float* flow_init = (const float*)d_in[2];
    const float* lc_w1 = (const float*)d_in[3];
    const float* lc_b1 = (const float*)d_in[4];
    const float* lc_w2 = (const float*)d_in[5];
    const float* lc_b2 = (const float*)d_in[6];
    const float* qw    = (const float*)d_in[7];
    const float* qb    = (const float*)d_in[8];
    const float* kw    = (const float*)d_in[9];
    const float* kb    = (const float*)d_in[10];
    const float* fr_w1 = (const float*)d_in[11];
    const float* fr_b1 = (const float*)d_in[12];
    const float* fr_w2 = (const float*)d_in[13];
    const float* fr_b2 = (const float*)d_in[14];
    const float* fr_w3 = (const float*)d_in[15];
    const float* fr_b3 = (const float*)d_in[16];
    const float* cf_w1 = (const float*)d_in[17];
    const float* cf_b1 = (const float*)d_in[18];
    const float* cf_w2 = (const float*)d_in[19];
    const float* cf_b2 = (const float*)d_in[20];
    const float* cf_w3 = (const float*)d_in[21];
    const float* cf_b3 = (const float*)d_in[22];

    float* lf0   = sym_addr(g_lf0);
    float* lf1   = sym_addr(g_lf1);
    float* tmp   = sym_addr(g_tmp);
    float* tmp2  = sym_addr(g_tmp2);
    float* xbuf  = sym_addr(g_x);
    float* ybuf  = sym_addr(g_y);
    float* flow  = sym_addr(g_flow);
    float* fi    = sym_addr(g_fi);
    float* hcat  = sym_addr(g_hcat);
    float* h2    = sym_addr(g_h2);
    float* Mbuf  = sym_addr(g_M);
    float* ubuf  = sym_addr(g_u);
    float* bvbuf = sym_addr(g_bv);
    float* cbuf  = sym_addr(g_c);
    float* bscal = sym_addr(g_bscal);
    float* Vbuf  = sym_addr(g_V);
    float* Mwbuf = sym_addr(g_Mw);
    float* U1    = sym_addr(g_U1);
    float* U2    = sym_addr(g_U2);
    float* Uc    = sym_addr(g_Uc);
    float* out_flow = (float*)d_out;
    float* out_conf = (float*)d_out + BATCH * 2 * NPIX;

    cudaFuncSetAttribute(fr_fused_kernel,
                         cudaFuncAttributeMaxDynamicSharedMemorySize, FR_SMEM_BYTES);
    cudaFuncSetAttribute(attn_tiled_kernel,
                         cudaFuncAttributeMaxDynamicSharedMemorySize, AT_SMEM_BYTES);

    // one-time preps
    prepM_kernel<<<128, 128>>>(qw, kw, Mbuf);
    prepUV_kernel<<<1, 128>>>(qw, kw, qb, kb, ubuf, bvbuf, cbuf);
    wino_wt_kernel<<<(128*128 + 255)/256, 256>>>(lc_w1, U1, 128, 128, 128);
    wino_wt_kernel<<<(128*128 + 255)/256, 256>>>(lc_w2, U2, 128, 128, 128);
    wino_wt_kernel<<<(264*128 + 255)/256, 256>>>(cf_w1, Uc, 258, 264, 128);

    // lc1 (both features, both batches)
    wino_in_kernel<<<dim3(NT_LC/32, 16), 256>>>(feat0, feat1, Vbuf, 128, 128, NT_LC, VPL_LC);
    wino_gemm_kernel<<<dim3(NT_LC/128, 16), 256>>>(U1, Vbuf, Mwbuf, 128, NT_LC, 128*128, VPL_LC, MPL_LC);
    wino_out_kernel<<<dim3(NT_LC/32, 16), 256>>>(Mwbuf, lc_b1, tmp, tmp2, 128, NT_LC, MPL_LC, ACT_GELU);
    // lc2
    wino_in_kernel<<<dim3(NT_LC/32, 16), 256>>>(tmp, tmp2, Vbuf, 128, 128, NT_LC, VPL_LC);
    wino_gemm_kernel<<<dim3(NT_LC/128, 16), 256>>>(U2, Vbuf, Mwbuf, 128, NT_LC, 128*128, VPL_LC, MPL_LC);
    wino_out_kernel<<<dim3(NT_LC/32, 16), 256>>>(Mwbuf, lc_b2, lf0, lf1, 128, NT_LC, MPL_LC, ACT_NONE);

    copy_kernel<<<(BATCH*2*NPIX + 255)/256, 256>>>(flow, flow_init, BATCH*2*NPIX);

    for (int it = 0; it < ITERS; ++it) {
        warp_diff_kernel<<<dim3(2*HW, BATCH), 128>>>(lf0, lf1, flow, xbuf);
        gemm_y_kernel<<<BATCH*NPIX/128, 256>>>(xbuf, Mbuf, bvbuf, ybuf, bscal);
        attn_tiled_kernel<<<dim3(4, 64, BATCH), 256, AT_SMEM_BYTES>>>(
            xbuf, ybuf, bscal, ubuf, cbuf, flow, fi);
        fr_fused_kernel<<<dim3(8,8,BATCH), 256, FR_SMEM_BYTES>>>(
            fi, fr_w1, fr_b1, fr_w2, fr_b2, fr_w3, fr_b3, flow);
    }

    // confidence head
    pack_kernel<<<dim3(HW, BATCH), 128>>>(feat0, feat1, flow, hcat);
    // cf1 via Winograd (Cin=258 -> pad 264)
    wino_in_kernel<<<dim3(NT_CF/32, 33), 256>>>(hcat, hcat, Vbuf, 258, 264, NT_CF, VPL_CF);
    wino_gemm_kernel<<<dim3(NT_CF/128, 16), 256>>>(Uc, Vbuf, Mwbuf, 264, NT_CF, 264*128, VPL_CF, MPL_CF);
    wino_out_kernel<<<dim3(NT_CF/32, 16), 256>>>(Mwbuf, cf_b1, tmp, tmp, 128, NT_CF, MPL_CF, ACT_GELU);
    // cf2 / cf3 direct
    conv3x3_kernel<16><<<dim3(4,4,BATCH*4), 256>>>(tmp, cf_w2, cf_b2, h2, 128, 64, ACT_GELU);
    conv3x3_kernel<2><<<dim3(4,4,BATCH), 256>>>(h2, cf_w3, cf_b3, out_conf, 64, 1, ACT_SIGM);

    copy_kernel<<<(BATCH*2*NPIX + 255)/256, 256>>>(out_flow, flow, BATCH*2*NPIX);
}